// round 5
// baseline (speedup 1.0000x reference)
#include <cuda_runtime.h>
#include <cuda_bf16.h>
#include <cstdint>
#include <math.h>

#define B_DIM 2
#define T_SEQ 2048
#define C_DIM 1024
#define H_DIM 16
#define D_HEAD 64
#define M_ROWS (B_DIM * T_SEQ)       // 4096
#define QKV_COLS (3 * C_DIM)         // 3072

// ---------------------------------------------------------------------------
// Scratch (allocation-free rule: __device__ globals)
// ---------------------------------------------------------------------------
__device__ float g_qkv[(size_t)M_ROWS * QKV_COLS];   // (B,T,3,H,D)
__device__ float g_y[(size_t)M_ROWS * C_DIM];        // attention output

__device__ __nv_bfloat16 g_xhi[(size_t)M_ROWS * C_DIM];
__device__ __nv_bfloat16 g_xlo[(size_t)M_ROWS * C_DIM];
__device__ __nv_bfloat16 g_wahi[(size_t)QKV_COLS * C_DIM];
__device__ __nv_bfloat16 g_walo[(size_t)QKV_COLS * C_DIM];
__device__ __nv_bfloat16 g_wphi[(size_t)C_DIM * C_DIM];
__device__ __nv_bfloat16 g_wplo[(size_t)C_DIM * C_DIM];
__device__ __nv_bfloat16 g_yhi[(size_t)M_ROWS * C_DIM];
__device__ __nv_bfloat16 g_ylo[(size_t)M_ROWS * C_DIM];

// head-major bf16 hi/lo Q,K,V: (B,H,T,D)
#define HD_ELEMS ((size_t)B_DIM * H_DIM * T_SEQ * D_HEAD)
__device__ __nv_bfloat16 g_Qhi[HD_ELEMS];
__device__ __nv_bfloat16 g_Qlo[HD_ELEMS];
__device__ __nv_bfloat16 g_Khi[HD_ELEMS];
__device__ __nv_bfloat16 g_Klo[HD_ELEMS];
__device__ __nv_bfloat16 g_Vhi[HD_ELEMS];
__device__ __nv_bfloat16 g_Vlo[HD_ELEMS];

// ---------------------------------------------------------------------------
// helpers
// ---------------------------------------------------------------------------
__device__ __forceinline__ uint32_t smem_to_u32(const void* smem_ptr) {
    uint32_t addr;
    asm("{ .reg .u64 tmp; cvta.to.shared.u64 tmp, %1; cvt.u32.u64 %0, tmp; }"
        : "=r"(addr) : "l"(smem_ptr));
    return addr;
}

#define CP_ASYNC16(dst_u32, src_ptr) \
    asm volatile("cp.async.cg.shared.global [%0], [%1], 16;" \
        :: "r"(dst_u32), "l"(__cvta_generic_to_global(src_ptr)))
#define CP_COMMIT() asm volatile("cp.async.commit_group;")
#define CP_WAIT1()  asm volatile("cp.async.wait_group 1;")
#define CP_WAIT0()  asm volatile("cp.async.wait_group 0;")

__device__ __forceinline__ void ldsm_x4(uint32_t* r, uint32_t addr) {
    asm volatile("ldmatrix.sync.aligned.m8n8.x4.shared.b16 {%0,%1,%2,%3}, [%4];"
        : "=r"(r[0]), "=r"(r[1]), "=r"(r[2]), "=r"(r[3]) : "r"(addr));
}
__device__ __forceinline__ void ldsm_x4t(uint32_t* r, uint32_t addr) {
    asm volatile("ldmatrix.sync.aligned.m8n8.x4.trans.shared.b16 {%0,%1,%2,%3}, [%4];"
        : "=r"(r[0]), "=r"(r[1]), "=r"(r[2]), "=r"(r[3]) : "r"(addr));
}

__device__ __forceinline__ void mma_bf16(float* d, const uint32_t* a, const uint32_t* b) {
    asm volatile(
        "mma.sync.aligned.m16n8k16.row.col.f32.bf16.bf16.f32 "
        "{%0,%1,%2,%3}, {%4,%5,%6,%7}, {%8,%9}, {%0,%1,%2,%3};"
        : "+f"(d[0]), "+f"(d[1]), "+f"(d[2]), "+f"(d[3])
        : "r"(a[0]), "r"(a[1]), "r"(a[2]), "r"(a[3]), "r"(b[0]), "r"(b[1]));
}

__device__ __forceinline__ void pack_hl(float a, float b, uint32_t& hi, uint32_t& lo) {
    __nv_bfloat162 h = __floats2bfloat162_rn(a, b);
    float ra = a - __bfloat162float(h.x);
    float rb = b - __bfloat162float(h.y);
    __nv_bfloat162 l = __floats2bfloat162_rn(ra, rb);
    hi = *(uint32_t*)&h;
    lo = *(uint32_t*)&l;
}

// ---------------------------------------------------------------------------
// fp32 -> bf16 hi/lo split (pre-pass; memory bound)
// ---------------------------------------------------------------------------
__global__ void split_kernel(const float* __restrict__ x,
                             __nv_bfloat16* __restrict__ hi,
                             __nv_bfloat16* __restrict__ lo, int n4)
{
    int i = blockIdx.x * blockDim.x + threadIdx.x;
    if (i >= n4) return;
    float4 v = ((const float4*)x)[i];
    __nv_bfloat162 h0 = __floats2bfloat162_rn(v.x, v.y);
    __nv_bfloat162 h1 = __floats2bfloat162_rn(v.z, v.w);
    __nv_bfloat162 l0 = __floats2bfloat162_rn(v.x - __bfloat162float(h0.x),
                                              v.y - __bfloat162float(h0.y));
    __nv_bfloat162 l1 = __floats2bfloat162_rn(v.z - __bfloat162float(h1.x),
                                              v.w - __bfloat162float(h1.y));
    ((__nv_bfloat162*)hi)[2 * i]     = h0;
    ((__nv_bfloat162*)hi)[2 * i + 1] = h1;
    ((__nv_bfloat162*)lo)[2 * i]     = l0;
    ((__nv_bfloat162*)lo)[2 * i + 1] = l1;
}

// ---------------------------------------------------------------------------
// Tensor-core GEMM NT via mma.sync (HMMA), bf16x3 compensated.
// v2: 128x128 CTA tile, 4 warps (2x2), 64x64 warp tile, BK=32,
// cp.async double buffer. 80B smem pitch -> conflict-free ldmatrix.
// ---------------------------------------------------------------------------
#define GTILE 10240u                  // 128 rows * 80B
#define GSTAGE (4 * GTILE)            // Ahi, Alo, Bhi, Blo
#define GEMM_SMEM (2 * GSTAGE)        // 81920 B

__device__ __forceinline__ void gemm_load_stage(
    uint32_t sdst,
    const __nv_bfloat16* __restrict__ Ahi, const __nv_bfloat16* __restrict__ Alo,
    const __nv_bfloat16* __restrict__ Bhi, const __nv_bfloat16* __restrict__ Blo,
    int bm, int bn, int K, int k0, int tid)
{
#pragma unroll
    for (int i = 0; i < 4; ++i) {
        int idx = tid + i * 128;           // 0..511 -> (row, 16B-chunk)
        int r = idx >> 2, c = idx & 3;
        uint32_t so = (uint32_t)(r * 80 + c * 16);
        size_t ga = (size_t)(bm + r) * K + k0 + c * 8;
        size_t gb = (size_t)(bn + r) * K + k0 + c * 8;
        CP_ASYNC16(sdst + so,              Ahi + ga);
        CP_ASYNC16(sdst + GTILE + so,      Alo + ga);
        CP_ASYNC16(sdst + 2 * GTILE + so,  Bhi + gb);
        CP_ASYNC16(sdst + 3 * GTILE + so,  Blo + gb);
    }
}

__global__ void __launch_bounds__(128) gemm_mma_kernel(
    const __nv_bfloat16* __restrict__ Ahi, const __nv_bfloat16* __restrict__ Alo,
    const __nv_bfloat16* __restrict__ Bhi, const __nv_bfloat16* __restrict__ Blo,
    float* __restrict__ C, int N, int K)
{
    extern __shared__ char smem[];
    const uint32_t sb = smem_to_u32(smem);
    const int tid = threadIdx.x;
    const int lane = tid & 31, wid = tid >> 5;
    const int wr = wid >> 1, wc = wid & 1;          // warp grid 2x2
    const int bm = blockIdx.y * 128, bn = blockIdx.x * 128;

    float acc[4][8][4];
#pragma unroll
    for (int mi = 0; mi < 4; ++mi)
#pragma unroll
        for (int ni = 0; ni < 8; ++ni)
#pragma unroll
            for (int j = 0; j < 4; ++j) acc[mi][ni][j] = 0.f;

    const int nk = K >> 5;
    gemm_load_stage(sb, Ahi, Alo, Bhi, Blo, bm, bn, K, 0, tid);
    CP_COMMIT();
    gemm_load_stage(sb + GSTAGE, Ahi, Alo, Bhi, Blo, bm, bn, K, 32, tid);
    CP_COMMIT();

    for (int ks = 0; ks < nk; ++ks) {
        CP_WAIT1();
        __syncthreads();
        const uint32_t sA = sb + (uint32_t)(ks & 1) * GSTAGE;
        const uint32_t sB = sA + 2 * GTILE;

#pragma unroll
        for (int kk = 0; kk < 2; ++kk) {
            const uint32_t colo = (uint32_t)(kk * 32 + (lane >> 4) * 16);
            uint32_t ahi[4][4], alo[4][4], bhi[8][2], blo[8][2];
#pragma unroll
            for (int mi = 0; mi < 4; ++mi) {
                uint32_t ro = (uint32_t)(wr * 64 + mi * 16 + (lane & 15)) * 80 + colo;
                ldsm_x4(ahi[mi], sA + ro);
                ldsm_x4(alo[mi], sA + GTILE + ro);
            }
#pragma unroll
            for (int nj = 0; nj < 4; ++nj) {
                uint32_t ro = (uint32_t)(wc * 64 + nj * 16 + (lane & 15)) * 80 + colo;
                uint32_t t[4], u[4];
                ldsm_x4(t, sB + ro);
                ldsm_x4(u, sB + GTILE + ro);
                bhi[nj * 2][0] = t[0]; bhi[nj * 2][1] = t[2];
                bhi[nj * 2 + 1][0] = t[1]; bhi[nj * 2 + 1][1] = t[3];
                blo[nj * 2][0] = u[0]; blo[nj * 2][1] = u[2];
                blo[nj * 2 + 1][0] = u[1]; blo[nj * 2 + 1][1] = u[3];
            }
#pragma unroll
            for (int mi = 0; mi < 4; ++mi)
#pragma unroll
                for (int ni = 0; ni < 8; ++ni)
                    mma_bf16(acc[mi][ni], ahi[mi], bhi[ni]);
#pragma unroll
            for (int mi = 0; mi < 4; ++mi)
#pragma unroll
                for (int ni = 0; ni < 8; ++ni)
                    mma_bf16(acc[mi][ni], alo[mi], bhi[ni]);
#pragma unroll
            for (int mi = 0; mi < 4; ++mi)
#pragma unroll
                for (int ni = 0; ni < 8; ++ni)
                    mma_bf16(acc[mi][ni], ahi[mi], blo[ni]);
        }

        __syncthreads();
        if (ks + 2 < nk)
            gemm_load_stage(sb + (uint32_t)(ks & 1) * GSTAGE, Ahi, Alo, Bhi, Blo,
                            bm, bn, K, (ks + 2) * 32, tid);
        CP_COMMIT();
    }

    // epilogue: direct fragment stores
#pragma unroll
    for (int mi = 0; mi < 4; ++mi) {
        int row = bm + wr * 64 + mi * 16 + (lane >> 2);
#pragma unroll
        for (int ni = 0; ni < 8; ++ni) {
            int col = bn + wc * 64 + ni * 8 + (lane & 3) * 2;
            float2 v0 = make_float2(acc[mi][ni][0], acc[mi][ni][1]);
            float2 v1 = make_float2(acc[mi][ni][2], acc[mi][ni][3]);
            *(float2*)&C[(size_t)row * N + col] = v0;
            *(float2*)&C[(size_t)(row + 8) * N + col] = v1;
        }
    }
}

// ---------------------------------------------------------------------------
// Prep: RoPE (q,k) + fp32->bf16 hi/lo split + head-major relayout (B,H,T,D).
// ---------------------------------------------------------------------------
__global__ void rope_split_kernel(const float* __restrict__ qkv,
                                  __nv_bfloat16* __restrict__ Qhi, __nv_bfloat16* __restrict__ Qlo,
                                  __nv_bfloat16* __restrict__ Khi, __nv_bfloat16* __restrict__ Klo,
                                  __nv_bfloat16* __restrict__ Vhi, __nv_bfloat16* __restrict__ Vlo)
{
    int idx = blockIdx.x * blockDim.x + threadIdx.x;
    int i = idx & 31;
    int h = (idx >> 5) & 15;
    int t = (idx >> 9) & 2047;
    int b = idx >> 20;

    float p = powf(10000.0f, (float)(2 * i) * (1.0f / 64.0f));
    float ang = (float)t * (1.0f / p);
    float sn, cs;
    sincosf(ang, &sn, &cs);

    size_t src = ((size_t)(b * T_SEQ + t)) * QKV_COLS + h * D_HEAD;
    size_t dst = ((size_t)((b * H_DIM + h) * T_SEQ + t)) * D_HEAD;

    // q (fold 1/8 scale)
    {
        float q1 = qkv[src + i], q2 = qkv[src + i + 32];
        float a = (q1 * cs + q2 * sn) * 0.125f;
        float c2 = (-q1 * sn + q2 * cs) * 0.125f;
        __nv_bfloat16 ha = __float2bfloat16(a), hc = __float2bfloat16(c2);
        Qhi[dst + i] = ha; Qhi[dst + i + 32] = hc;
        Qlo[dst + i] = __float2bfloat16(a - __bfloat162float(ha));
        Qlo[dst + i + 32] = __float2bfloat16(c2 - __bfloat162float(hc));
    }
    // k
    {
        float k1 = qkv[src + C_DIM + i], k2 = qkv[src + C_DIM + i + 32];
        float a = k1 * cs + k2 * sn;
        float c2 = -k1 * sn + k2 * cs;
        __nv_bfloat16 ha = __float2bfloat16(a), hc = __float2bfloat16(c2);
        Khi[dst + i] = ha; Khi[dst + i + 32] = hc;
        Klo[dst + i] = __float2bfloat16(a - __bfloat162float(ha));
        Klo[dst + i + 32] = __float2bfloat16(c2 - __bfloat162float(hc));
    }
    // v (plain split)
    {
        float v1 = qkv[src + 2 * C_DIM + i], v2 = qkv[src + 2 * C_DIM + i + 32];
        __nv_bfloat16 ha = __float2bfloat16(v1), hc = __float2bfloat16(v2);
        Vhi[dst + i] = ha; Vhi[dst + i + 32] = hc;
        Vlo[dst + i] = __float2bfloat16(v1 - __bfloat162float(ha));
        Vlo[dst + i + 32] = __float2bfloat16(v2 - __bfloat162float(hc));
    }
}

// ---------------------------------------------------------------------------
// Flash attention via mma.sync, causal, bf16 hi/lo 3-pass.
// CTA: 128 queries x one (b,h); 8 warps x 16 rows. 64-key tiles, double buffer.
// ---------------------------------------------------------------------------
#define FPITCH 144u
#define FTILE  (64u * FPITCH)          // 9216
#define FSTAGE (4u * FTILE)            // Khi, Klo, Vhi, Vlo = 36864
#define FL_SMEM (2u * FSTAGE)          // 73728

__device__ __forceinline__ void flash_load_stage(
    uint32_t dstbase, int kb,
    const __nv_bfloat16* __restrict__ Kh, const __nv_bfloat16* __restrict__ Kl,
    const __nv_bfloat16* __restrict__ Vh, const __nv_bfloat16* __restrict__ Vl,
    int tid)
{
    // 2048 16B-chunks: 4 tiles * 64 rows * 8 chunks
#pragma unroll
    for (int j = 0; j < 8; ++j) {
        int idx = tid + j * 256;
        int tile = idx >> 9;                   // 0..3
        int r = (idx >> 3) & 63;
        int c = idx & 7;
        uint32_t dst = dstbase + (uint32_t)tile * FTILE + (uint32_t)r * FPITCH + c * 16;
        const __nv_bfloat16* src =
            (tile == 0 ? Kh : tile == 1 ? Kl : tile == 2 ? Vh : Vl);
        CP_ASYNC16(dst, src + (size_t)(kb + r) * D_HEAD + c * 8);
    }
}

__global__ void __launch_bounds__(256) flash_mma_kernel(
    const __nv_bfloat16* __restrict__ Qhi, const __nv_bfloat16* __restrict__ Qlo,
    const __nv_bfloat16* __restrict__ Khi, const __nv_bfloat16* __restrict__ Klo,
    const __nv_bfloat16* __restrict__ Vhi, const __nv_bfloat16* __restrict__ Vlo,
    float* __restrict__ y)
{
    extern __shared__ char fsm[];
    const uint32_t sb = smem_to_u32(fsm);
    const int tid = threadIdx.x;
    const int lane = tid & 31, w = tid >> 5;
    const int qt = gridDim.x - 1 - blockIdx.x;     // heavy tiles first
    const int bh = blockIdx.y;
    const int qb = qt * 128;

    const size_t hoff = (size_t)bh * T_SEQ * D_HEAD;
    const __nv_bfloat16* Qh = Qhi + hoff + (size_t)qb * D_HEAD;
    const __nv_bfloat16* Ql = Qlo + hoff + (size_t)qb * D_HEAD;
    const __nv_bfloat16* Kh = Khi + hoff;
    const __nv_bfloat16* Kl = Klo + hoff;
    const __nv_bfloat16* Vh = Vhi + hoff;
    const __nv_bfloat16* Vl = Vlo + hoff;

    // ---- stage Q (hi at sb, lo at sb+128*FPITCH) and extract A fragments ----
#pragma unroll
    for (int j = 0; j < 8; ++j) {
        int idx = tid + j * 256;               // 2048 chunks
        int tile = idx >> 10;
        int r = (idx >> 3) & 127;
        int c = idx & 7;
        uint32_t dst = sb + (uint32_t)tile * (128u * FPITCH) + (uint32_t)r * FPITCH + c * 16;
        const __nv_bfloat16* src = (tile == 0 ? Qh : Ql);
        CP_ASYNC16(dst, src + (size_t)r * D_HEAD + c * 8);
    }
    CP_COMMIT();
    CP_WAIT0();
    __syncthreads();

    uint32_t qhf[4][4], qlf[4][4];
    {
        uint32_t arow = (uint32_t)(w * 16 + (lane & 7) + ((lane & 8) ? 8 : 0));
        uint32_t acol = (uint32_t)(((lane & 16) ? 16 : 0));
#pragma unroll
        for (int kk = 0; kk < 4; ++kk) {
            uint32_t a = sb + arow * FPITCH + kk * 32 + acol;
            ldsm_x4(qhf[kk], a);
            ldsm_x4(qlf[kk], a + 128u * FPITCH);
        }
    }
    __syncthreads();   // Q fragments extracted; smem reusable

    float o[8][4];
#pragma unroll
    for (int j = 0; j < 8; ++j)
#pragma unroll
        for (int c = 0; c < 4; ++c) o[j][c] = 0.f;
    float m0 = -1e30f, m1 = -1e30f, l0 = 0.f, l1 = 0.f;

    const int ntiles = 2 * qt + 2;
    const int wqmin = qb + w * 16;
    const int wqmax = wqmin + 15;

    flash_load_stage(sb, 0, Kh, Kl, Vh, Vl, tid);
    CP_COMMIT();
    flash_load_stage(sb + FSTAGE, 64, Kh, Kl, Vh, Vl, tid);
    CP_COMMIT();

    for (int kt = 0; kt < ntiles; ++kt) {
        CP_WAIT1();
        __syncthreads();
        const uint32_t stage = sb + (uint32_t)(kt & 1) * FSTAGE;
        const int kb = kt * 64;

        if (kb <= wqmax) {
            // ---- S = Q K^T (3-pass hi/lo) ----
            float s[8][4];
#pragma unroll
            for (int j = 0; j < 8; ++j)
#pragma unroll
                for (int c = 0; c < 4; ++c) s[j][c] = 0.f;

            const uint32_t br = (uint32_t)((lane & 7) + ((lane & 16) ? 8 : 0));
            const uint32_t bc = (uint32_t)((lane & 8) ? 16 : 0);
#pragma unroll
            for (int kg = 0; kg < 4; ++kg) {
                uint32_t rowa = (uint32_t)(kg * 16) + br;
#pragma unroll
                for (int kk = 0; kk < 4; ++kk) {
                    uint32_t addr = stage + rowa * FPITCH + kk * 32 + bc;
                    uint32_t kh4[4], kl4[4];
                    ldsm_x4(kh4, addr);
                    ldsm_x4(kl4, addr + FTILE);
                    mma_bf16(s[2 * kg],     qhf[kk], &kh4[0]);
                    mma_bf16(s[2 * kg + 1], qhf[kk], &kh4[2]);
                    mma_bf16(s[2 * kg],     qlf[kk], &kh4[0]);
                    mma_bf16(s[2 * kg + 1], qlf[kk], &kh4[2]);
                    mma_bf16(s[2 * kg],     qhf[kk], &kl4[0]);
                    mma_bf16(s[2 * kg + 1], qhf[kk], &kl4[2]);
                }
            }

            // ---- causal mask ----
            if (kb + 63 > wqmin) {
                int r0 = wqmin + (lane >> 2), r1 = r0 + 8;
#pragma unroll
                for (int j = 0; j < 8; ++j) {
                    int k0 = kb + j * 8 + ((lane & 3) << 1);
                    if (k0 > r0)     s[j][0] = -1e30f;
                    if (k0 + 1 > r0) s[j][1] = -1e30f;
                    if (k0 > r1)     s[j][2] = -1e30f;
                    if (k0 + 1 > r1) s[j][3] = -1e30f;
                }
            }

            // ---- online softmax ----
            float mx0 = -1e30f, mx1 = -1e30f;
#pragma unroll
            for (int j = 0; j < 8; ++j) {
                mx0 = fmaxf(mx0, fmaxf(s[j][0], s[j][1]));
                mx1 = fmaxf(mx1, fmaxf(s[j][2], s[j][3]));
            }
            mx0 = fmaxf(mx0, __shfl_xor_sync(0xffffffffu, mx0, 1));
            mx0 = fmaxf(mx0, __shfl_xor_sync(0xffffffffu, mx0, 2));
            mx1 = fmaxf(mx1, __shfl_xor_sync(0xffffffffu, mx1, 1));
            mx1 = fmaxf(mx1, __shfl_xor_sync(0xffffffffu, mx1, 2));
            float m0n = fmaxf(m0, mx0), m1n = fmaxf(m1, mx1);
            float sc0 = __expf(m0 - m0n), sc1 = __expf(m1 - m1n);
            float rs0 = 0.f, rs1 = 0.f;
#pragma unroll
            for (int j = 0; j < 8; ++j) {
                s[j][0] = __expf(s[j][0] - m0n);
                s[j][1] = __expf(s[j][1] - m0n);
                s[j][2] = __expf(s[j][2] - m1n);
                s[j][3] = __expf(s[j][3] - m1n);
                rs0 += s[j][0] + s[j][1];
                rs1 += s[j][2] + s[j][3];
            }
            rs0 += __shfl_xor_sync(0xffffffffu, rs0, 1);
            rs0 += __shfl_xor_sync(0xffffffffu, rs0, 2);
            rs1 += __shfl_xor_sync(0xffffffffu, rs1, 1);
            rs1 += __shfl_xor_sync(0xffffffffu, rs1, 2);
            l0 = l0 * sc0 + rs0;
            l1 = l1 * sc1 + rs1;
            m0 = m0n; m1 = m1n;
#pragma unroll
            for (int j = 0; j < 8; ++j) {
                o[j][0] *= sc0; o[j][1] *= sc0;
                o[j][2] *= sc1; o[j][3] *= sc1;
            }

            // ---- pack P hi/lo A-fragments ----
            uint32_t aph[4][4], apl[4][4];
#pragma unroll
            for (int kk2 = 0; kk2 < 4; ++kk2) {
                int j0 = 2 * kk2, j1 = j0 + 1;
                pack_hl(s[j0][0], s[j0][1], aph[kk2][0], apl[kk2][0]);
                pack_hl(s[j0][2], s[j0][3], aph[kk2][1], apl[kk2][1]);
                pack_hl(s[j1][0], s[j1][1], aph[kk2][2], apl[kk2][2]);
                pack_hl(s[j1][2], s[j1][3], aph[kk2][3], apl[kk2][3]);
            }

            // ---- O += P V (3-pass) via ldmatrix.trans on V ----
            const uint32_t vr = (uint32_t)((lane & 7) + ((lane & 8) ? 8 : 0));
            const uint32_t vc = (uint32_t)((lane & 16) ? 16 : 0);
#pragma unroll
            for (int dg = 0; dg < 4; ++dg) {
#pragma unroll
                for (int kk2 = 0; kk2 < 4; ++kk2) {
                    uint32_t addr = stage + 2 * FTILE +
                                    (uint32_t)(kk2 * 16 + vr) * FPITCH + dg * 32 + vc;
                    uint32_t vh4[4], vl4[4];
                    ldsm_x4t(vh4, addr);
                    ldsm_x4t(vl4, addr + FTILE);
                    mma_bf16(o[2 * dg],     aph[kk2], &vh4[0]);
                    mma_bf16(o[2 * dg + 1], aph[kk2], &vh4[2]);
                    mma_bf16(o[2 * dg],     apl[kk2], &vh4[0]);
                    mma_bf16(o[2 * dg + 1], apl[kk2], &vh4[2]);
                    mma_bf16(o[2 * dg],     aph[kk2], &vl4[0]);
                    mma_bf16(o[2 * dg + 1], aph[kk2], &vl4[2]);
                }
            }
        }

        __syncthreads();
        if (kt + 2 < ntiles)
            flash_load_stage(sb + (uint32_t)(kt & 1) * FSTAGE, (kt + 2) * 64,
                             Kh, Kl, Vh, Vl, tid);
        CP_COMMIT();
    }

    // ---- normalize and write ----
    const float inv0 = 1.0f / l0, inv1 = 1.0f / l1;
    const int b = bh >> 4, h = bh & 15;
    const int r0 = qb + w * 16 + (lane >> 2);
#pragma unroll
    for (int j = 0; j < 8; ++j) {
        int col = h * 64 + j * 8 + (lane & 3) * 2;
        float2 v0 = make_float2(o[j][0] * inv0, o[j][1] * inv0);
        float2 v1 = make_float2(o[j][2] * inv1, o[j][3] * inv1);
        *(float2*)&y[(size_t)(b * T_SEQ + r0) * C_DIM + col] = v0;
        *(float2*)&y[(size_t)(b * T_SEQ + r0 + 8) * C_DIM + col] = v1;
    }
}

// ---------------------------------------------------------------------------
extern "C" void kernel_launch(void* const* d_in, const int* in_sizes, int n_in,
                              void* d_out, int out_size)
{
    const float* x      = (const float*)d_in[0];
    const float* w_attn = (const float*)d_in[1];
    const float* w_proj = (const float*)d_in[2];
    float* out = (float*)d_out;

    float *qkv, *y;
    __nv_bfloat16 *xhi, *xlo, *wahi, *walo, *wphi, *wplo, *yhi, *ylo;
    __nv_bfloat16 *Qhi, *Qlo, *Khi, *Klo, *Vhi, *Vlo;
    cudaGetSymbolAddress((void**)&qkv, g_qkv);
    cudaGetSymbolAddress((void**)&y, g_y);
    cudaGetSymbolAddress((void**)&xhi, g_xhi);
    cudaGetSymbolAddress((void**)&xlo, g_xlo);
    cudaGetSymbolAddress((void**)&wahi, g_wahi);
    cudaGetSymbolAddress((void**)&walo, g_walo);
    cudaGetSymbolAddress((void**)&wphi, g_wphi);
    cudaGetSymbolAddress((void**)&wplo, g_wplo);
    cudaGetSymbolAddress((void**)&yhi, g_yhi);
    cudaGetSymbolAddress((void**)&ylo, g_ylo);
    cudaGetSymbolAddress((void**)&Qhi, g_Qhi);
    cudaGetSymbolAddress((void**)&Qlo, g_Qlo);
    cudaGetSymbolAddress((void**)&Khi, g_Khi);
    cudaGetSymbolAddress((void**)&Klo, g_Klo);
    cudaGetSymbolAddress((void**)&Vhi, g_Vhi);
    cudaGetSymbolAddress((void**)&Vlo, g_Vlo);

    static bool attr_set = false;
    if (!attr_set) {
        cudaFuncSetAttribute(gemm_mma_kernel,
                             cudaFuncAttributeMaxDynamicSharedMemorySize, GEMM_SMEM);
        cudaFuncSetAttribute(flash_mma_kernel,
                             cudaFuncAttributeMaxDynamicSharedMemorySize, FL_SMEM);
        attr_set = true;
    }

    // input splits
    {
        int n4 = M_ROWS * C_DIM / 4;
        split_kernel<<<(n4 + 255) / 256, 256>>>(x, xhi, xlo, n4);
        n4 = QKV_COLS * C_DIM / 4;
        split_kernel<<<(n4 + 255) / 256, 256>>>(w_attn, wahi, walo, n4);
        n4 = C_DIM * C_DIM / 4;
        split_kernel<<<(n4 + 255) / 256, 256>>>(w_proj, wphi, wplo, n4);
    }
    // 1) qkv = x @ w_attn^T
    {
        dim3 grid(QKV_COLS / 128, M_ROWS / 128);
        gemm_mma_kernel<<<grid, 128, GEMM_SMEM>>>(xhi, xlo, wahi, walo, qkv,
                                                  QKV_COLS, C_DIM);
    }
    // 2) RoPE + split + relayout
    {
        int total = B_DIM * T_SEQ * H_DIM * 32;
        rope_split_kernel<<<total / 256, 256>>>(qkv, Qhi, Qlo, Khi, Klo, Vhi, Vlo);
    }
    // 3) flash attention (tensor cores) -> y
    {
        dim3 grid(T_SEQ / 128, B_DIM * H_DIM);
        flash_mma_kernel<<<grid, 256, FL_SMEM>>>(Qhi, Qlo, Khi, Klo, Vhi, Vlo, y);
    }
    // 4) out = y @ w_proj^T
    {
        int n4 = M_ROWS * C_DIM / 4;
        split_kernel<<<(n4 + 255) / 256, 256>>>(y, yhi, ylo, n4);
        dim3 grid(C_DIM / 128, M_ROWS / 128);
        gemm_mma_kernel<<<grid, 128, GEMM_SMEM>>>(yhi, ylo, wphi, wplo, out,
                                                  C_DIM, C_DIM);
    }
}

// round 6
// speedup vs baseline: 1.2497x; 1.2497x over previous
#include <cuda_runtime.h>
#include <cuda_bf16.h>
#include <cuda_fp16.h>
#include <cstdint>
#include <math.h>

#define B_DIM 2
#define T_SEQ 2048
#define C_DIM 1024
#define H_DIM 16
#define D_HEAD 64
#define M_ROWS (B_DIM * T_SEQ)       // 4096
#define QKV_COLS (3 * C_DIM)         // 3072

// ---------------------------------------------------------------------------
// Scratch (allocation-free rule: __device__ globals)
// ---------------------------------------------------------------------------
__device__ float g_qkv[(size_t)M_ROWS * QKV_COLS];   // (B,T,3,H,D)

// fp16 GEMM operands
__device__ __half g_xhi[(size_t)M_ROWS * C_DIM];
__device__ __half g_xlo[(size_t)M_ROWS * C_DIM];
__device__ __half g_wa [(size_t)QKV_COLS * C_DIM];   // w_attn fp16 (hi only)
__device__ __half g_wp [(size_t)C_DIM * C_DIM];      // w_proj fp16 (hi only)
__device__ __half g_yhi[(size_t)M_ROWS * C_DIM];
__device__ __half g_ylo[(size_t)M_ROWS * C_DIM];

// head-major bf16 hi/lo Q,K,V: (B,H,T,D)
#define HD_ELEMS ((size_t)B_DIM * H_DIM * T_SEQ * D_HEAD)
__device__ __nv_bfloat16 g_Qhi[HD_ELEMS];
__device__ __nv_bfloat16 g_Qlo[HD_ELEMS];
__device__ __nv_bfloat16 g_Khi[HD_ELEMS];
__device__ __nv_bfloat16 g_Klo[HD_ELEMS];
__device__ __nv_bfloat16 g_Vhi[HD_ELEMS];
__device__ __nv_bfloat16 g_Vlo[HD_ELEMS];

// ---------------------------------------------------------------------------
// helpers
// ---------------------------------------------------------------------------
__device__ __forceinline__ uint32_t smem_to_u32(const void* smem_ptr) {
    uint32_t addr;
    asm("{ .reg .u64 tmp; cvta.to.shared.u64 tmp, %1; cvt.u32.u64 %0, tmp; }"
        : "=r"(addr) : "l"(smem_ptr));
    return addr;
}

#define CP_ASYNC16(dst_u32, src_ptr) \
    asm volatile("cp.async.cg.shared.global [%0], [%1], 16;" \
        :: "r"(dst_u32), "l"(__cvta_generic_to_global(src_ptr)))
#define CP_COMMIT() asm volatile("cp.async.commit_group;")
#define CP_WAIT1()  asm volatile("cp.async.wait_group 1;")
#define CP_WAIT0()  asm volatile("cp.async.wait_group 0;")

__device__ __forceinline__ void ldsm_x4(uint32_t* r, uint32_t addr) {
    asm volatile("ldmatrix.sync.aligned.m8n8.x4.shared.b16 {%0,%1,%2,%3}, [%4];"
        : "=r"(r[0]), "=r"(r[1]), "=r"(r[2]), "=r"(r[3]) : "r"(addr));
}
__device__ __forceinline__ void ldsm_x4t(uint32_t* r, uint32_t addr) {
    asm volatile("ldmatrix.sync.aligned.m8n8.x4.trans.shared.b16 {%0,%1,%2,%3}, [%4];"
        : "=r"(r[0]), "=r"(r[1]), "=r"(r[2]), "=r"(r[3]) : "r"(addr));
}

__device__ __forceinline__ void mma_bf16(float* d, const uint32_t* a, const uint32_t* b) {
    asm volatile(
        "mma.sync.aligned.m16n8k16.row.col.f32.bf16.bf16.f32 "
        "{%0,%1,%2,%3}, {%4,%5,%6,%7}, {%8,%9}, {%0,%1,%2,%3};"
        : "+f"(d[0]), "+f"(d[1]), "+f"(d[2]), "+f"(d[3])
        : "r"(a[0]), "r"(a[1]), "r"(a[2]), "r"(a[3]), "r"(b[0]), "r"(b[1]));
}
__device__ __forceinline__ void mma_f16(float* d, const uint32_t* a, const uint32_t* b) {
    asm volatile(
        "mma.sync.aligned.m16n8k16.row.col.f32.f16.f16.f32 "
        "{%0,%1,%2,%3}, {%4,%5,%6,%7}, {%8,%9}, {%0,%1,%2,%3};"
        : "+f"(d[0]), "+f"(d[1]), "+f"(d[2]), "+f"(d[3])
        : "r"(a[0]), "r"(a[1]), "r"(a[2]), "r"(a[3]), "r"(b[0]), "r"(b[1]));
}

__device__ __forceinline__ void pack_hl(float a, float b, uint32_t& hi, uint32_t& lo) {
    __nv_bfloat162 h = __floats2bfloat162_rn(a, b);
    float ra = a - __bfloat162float(h.x);
    float rb = b - __bfloat162float(h.y);
    __nv_bfloat162 l = __floats2bfloat162_rn(ra, rb);
    hi = *(uint32_t*)&h;
    lo = *(uint32_t*)&l;
}

// ---------------------------------------------------------------------------
// fp32 -> fp16 hi/lo split (for activations)
// ---------------------------------------------------------------------------
__global__ void split_f16_kernel(const float* __restrict__ x,
                                 __half* __restrict__ hi,
                                 __half* __restrict__ lo, int n4)
{
    int i = blockIdx.x * blockDim.x + threadIdx.x;
    if (i >= n4) return;
    float4 v = ((const float4*)x)[i];
    __half h0 = __float2half_rn(v.x), h1 = __float2half_rn(v.y);
    __half h2 = __float2half_rn(v.z), h3 = __float2half_rn(v.w);
    __half l0 = __float2half_rn(v.x - __half2float(h0));
    __half l1 = __float2half_rn(v.y - __half2float(h1));
    __half l2 = __float2half_rn(v.z - __half2float(h2));
    __half l3 = __float2half_rn(v.w - __half2float(h3));
    __half2 hp0 = {h0, h1}, hp1 = {h2, h3};
    __half2 lp0 = {l0, l1}, lp1 = {l2, l3};
    ((__half2*)hi)[2 * i]     = hp0;
    ((__half2*)hi)[2 * i + 1] = hp1;
    ((__half2*)lo)[2 * i]     = lp0;
    ((__half2*)lo)[2 * i + 1] = lp1;
}

// fp32 -> fp16 convert (for weights; lo dropped by design)
__global__ void conv_f16_kernel(const float* __restrict__ x,
                                __half* __restrict__ hi, int n4)
{
    int i = blockIdx.x * blockDim.x + threadIdx.x;
    if (i >= n4) return;
    float4 v = ((const float4*)x)[i];
    __half2 hp0 = {__float2half_rn(v.x), __float2half_rn(v.y)};
    __half2 hp1 = {__float2half_rn(v.z), __float2half_rn(v.w)};
    ((__half2*)hi)[2 * i]     = hp0;
    ((__half2*)hi)[2 * i + 1] = hp1;
}

// ---------------------------------------------------------------------------
// Tensor-core GEMM NT via mma.sync fp16, 2-pass compensated:
//   C[M,N] = (Ahi+Alo)[M,K] * Bhi[N,K]^T
// 128x128 CTA tile, BK=32, 256 threads (8 warps 2x4, 64x32 warp tiles),
// cp.async double buffer, 80B smem pitch.
// ---------------------------------------------------------------------------
#define GTILE 10240u                  // 128 rows * 80B
#define GSTAGE (3 * GTILE)            // Ahi, Alo, Bhi
#define GEMM_SMEM (2 * GSTAGE)        // 61440 B

__device__ __forceinline__ void gemm_load_stage(
    uint32_t sdst,
    const __half* __restrict__ Ahi, const __half* __restrict__ Alo,
    const __half* __restrict__ Bhi,
    int bm, int bn, int K, int k0, int tid)
{
#pragma unroll
    for (int i = 0; i < 2; ++i) {
        int idx = tid + i * 256;           // 0..511 -> (row, 16B-chunk)
        int r = idx >> 2, c = idx & 3;
        uint32_t so = (uint32_t)(r * 80 + c * 16);
        size_t ga = (size_t)(bm + r) * K + k0 + c * 8;
        size_t gb = (size_t)(bn + r) * K + k0 + c * 8;
        CP_ASYNC16(sdst + so,              Ahi + ga);
        CP_ASYNC16(sdst + GTILE + so,      Alo + ga);
        CP_ASYNC16(sdst + 2 * GTILE + so,  Bhi + gb);
    }
}

__global__ void __launch_bounds__(256) gemm_f16_kernel(
    const __half* __restrict__ Ahi, const __half* __restrict__ Alo,
    const __half* __restrict__ Bhi,
    float* __restrict__ C, int N, int K)
{
    extern __shared__ char smem[];
    const uint32_t sb = smem_to_u32(smem);
    const int tid = threadIdx.x;
    const int lane = tid & 31, wid = tid >> 5;
    const int wr = wid >> 2, wc = wid & 3;          // warp grid 2x4
    const int bm = blockIdx.y * 128, bn = blockIdx.x * 128;

    float acc[4][4][4];
#pragma unroll
    for (int mi = 0; mi < 4; ++mi)
#pragma unroll
        for (int ni = 0; ni < 4; ++ni)
#pragma unroll
            for (int j = 0; j < 4; ++j) acc[mi][ni][j] = 0.f;

    const int nk = K >> 5;
    gemm_load_stage(sb, Ahi, Alo, Bhi, bm, bn, K, 0, tid);
    CP_COMMIT();
    gemm_load_stage(sb + GSTAGE, Ahi, Alo, Bhi, bm, bn, K, 32, tid);
    CP_COMMIT();

    for (int ks = 0; ks < nk; ++ks) {
        CP_WAIT1();
        __syncthreads();
        const uint32_t sA = sb + (uint32_t)(ks & 1) * GSTAGE;
        const uint32_t sB = sA + 2 * GTILE;

#pragma unroll
        for (int kk = 0; kk < 2; ++kk) {
            const uint32_t colo = (uint32_t)(kk * 32 + (lane >> 4) * 16);
            uint32_t ahi[4][4], alo[4][4], bhi[4][2];
#pragma unroll
            for (int mi = 0; mi < 4; ++mi) {
                uint32_t ro = (uint32_t)(wr * 64 + mi * 16 + (lane & 15)) * 80 + colo;
                ldsm_x4(ahi[mi], sA + ro);
                ldsm_x4(alo[mi], sA + GTILE + ro);
            }
#pragma unroll
            for (int nj = 0; nj < 2; ++nj) {
                uint32_t ro = (uint32_t)(wc * 32 + nj * 16 + (lane & 15)) * 80 + colo;
                uint32_t t[4];
                ldsm_x4(t, sB + ro);
                bhi[nj * 2][0] = t[0]; bhi[nj * 2][1] = t[2];
                bhi[nj * 2 + 1][0] = t[1]; bhi[nj * 2 + 1][1] = t[3];
            }
#pragma unroll
            for (int mi = 0; mi < 4; ++mi)
#pragma unroll
                for (int ni = 0; ni < 4; ++ni)
                    mma_f16(acc[mi][ni], ahi[mi], bhi[ni]);
#pragma unroll
            for (int mi = 0; mi < 4; ++mi)
#pragma unroll
                for (int ni = 0; ni < 4; ++ni)
                    mma_f16(acc[mi][ni], alo[mi], bhi[ni]);
        }

        __syncthreads();
        if (ks + 2 < nk)
            gemm_load_stage(sb + (uint32_t)(ks & 1) * GSTAGE, Ahi, Alo, Bhi,
                            bm, bn, K, (ks + 2) * 32, tid);
        CP_COMMIT();
    }

    // epilogue: direct fragment stores
#pragma unroll
    for (int mi = 0; mi < 4; ++mi) {
        int row = bm + wr * 64 + mi * 16 + (lane >> 2);
#pragma unroll
        for (int ni = 0; ni < 4; ++ni) {
            int col = bn + wc * 32 + ni * 8 + (lane & 3) * 2;
            float2 v0 = make_float2(acc[mi][ni][0], acc[mi][ni][1]);
            float2 v1 = make_float2(acc[mi][ni][2], acc[mi][ni][3]);
            *(float2*)&C[(size_t)row * N + col] = v0;
            *(float2*)&C[(size_t)(row + 8) * N + col] = v1;
        }
    }
}

// ---------------------------------------------------------------------------
// Prep: RoPE (q,k) + fp32->bf16 hi/lo split + head-major relayout (B,H,T,D).
// ---------------------------------------------------------------------------
__global__ void rope_split_kernel(const float* __restrict__ qkv,
                                  __nv_bfloat16* __restrict__ Qhi, __nv_bfloat16* __restrict__ Qlo,
                                  __nv_bfloat16* __restrict__ Khi, __nv_bfloat16* __restrict__ Klo,
                                  __nv_bfloat16* __restrict__ Vhi, __nv_bfloat16* __restrict__ Vlo)
{
    int idx = blockIdx.x * blockDim.x + threadIdx.x;
    int i = idx & 31;
    int h = (idx >> 5) & 15;
    int t = (idx >> 9) & 2047;
    int b = idx >> 20;

    float p = powf(10000.0f, (float)(2 * i) * (1.0f / 64.0f));
    float ang = (float)t * (1.0f / p);
    float sn, cs;
    sincosf(ang, &sn, &cs);

    size_t src = ((size_t)(b * T_SEQ + t)) * QKV_COLS + h * D_HEAD;
    size_t dst = ((size_t)((b * H_DIM + h) * T_SEQ + t)) * D_HEAD;

    // q (fold 1/8 scale)
    {
        float q1 = qkv[src + i], q2 = qkv[src + i + 32];
        float a = (q1 * cs + q2 * sn) * 0.125f;
        float c2 = (-q1 * sn + q2 * cs) * 0.125f;
        __nv_bfloat16 ha = __float2bfloat16(a), hc = __float2bfloat16(c2);
        Qhi[dst + i] = ha; Qhi[dst + i + 32] = hc;
        Qlo[dst + i] = __float2bfloat16(a - __bfloat162float(ha));
        Qlo[dst + i + 32] = __float2bfloat16(c2 - __bfloat162float(hc));
    }
    // k
    {
        float k1 = qkv[src + C_DIM + i], k2 = qkv[src + C_DIM + i + 32];
        float a = k1 * cs + k2 * sn;
        float c2 = -k1 * sn + k2 * cs;
        __nv_bfloat16 ha = __float2bfloat16(a), hc = __float2bfloat16(c2);
        Khi[dst + i] = ha; Khi[dst + i + 32] = hc;
        Klo[dst + i] = __float2bfloat16(a - __bfloat162float(ha));
        Klo[dst + i + 32] = __float2bfloat16(c2 - __bfloat162float(hc));
    }
    // v (plain split)
    {
        float v1 = qkv[src + 2 * C_DIM + i], v2 = qkv[src + 2 * C_DIM + i + 32];
        __nv_bfloat16 ha = __float2bfloat16(v1), hc = __float2bfloat16(v2);
        Vhi[dst + i] = ha; Vhi[dst + i + 32] = hc;
        Vlo[dst + i] = __float2bfloat16(v1 - __bfloat162float(ha));
        Vlo[dst + i + 32] = __float2bfloat16(v2 - __bfloat162float(hc));
    }
}

// ---------------------------------------------------------------------------
// Flash attention via mma.sync, causal, bf16 hi/lo 3-pass.
// CTA: 128 queries x one (b,h); 8 warps x 16 rows. 64-key tiles, double buffer.
// Epilogue writes fp16 hi/lo directly (proj GEMM input).
// ---------------------------------------------------------------------------
#define FPITCH 144u
#define FTILE  (64u * FPITCH)          // 9216
#define FSTAGE (4u * FTILE)            // Khi, Klo, Vhi, Vlo = 36864
#define FL_SMEM (2u * FSTAGE)          // 73728

__device__ __forceinline__ void flash_load_stage(
    uint32_t dstbase, int kb,
    const __nv_bfloat16* __restrict__ Kh, const __nv_bfloat16* __restrict__ Kl,
    const __nv_bfloat16* __restrict__ Vh, const __nv_bfloat16* __restrict__ Vl,
    int tid)
{
#pragma unroll
    for (int j = 0; j < 8; ++j) {
        int idx = tid + j * 256;
        int tile = idx >> 9;                   // 0..3
        int r = (idx >> 3) & 63;
        int c = idx & 7;
        uint32_t dst = dstbase + (uint32_t)tile * FTILE + (uint32_t)r * FPITCH + c * 16;
        const __nv_bfloat16* src =
            (tile == 0 ? Kh : tile == 1 ? Kl : tile == 2 ? Vh : Vl);
        CP_ASYNC16(dst, src + (size_t)(kb + r) * D_HEAD + c * 8);
    }
}

__global__ void __launch_bounds__(256) flash_mma_kernel(
    const __nv_bfloat16* __restrict__ Qhi, const __nv_bfloat16* __restrict__ Qlo,
    const __nv_bfloat16* __restrict__ Khi, const __nv_bfloat16* __restrict__ Klo,
    const __nv_bfloat16* __restrict__ Vhi, const __nv_bfloat16* __restrict__ Vlo,
    __half* __restrict__ yhi, __half* __restrict__ ylo)
{
    extern __shared__ char fsm[];
    const uint32_t sb = smem_to_u32(fsm);
    const int tid = threadIdx.x;
    const int lane = tid & 31, w = tid >> 5;
    const int qt = gridDim.x - 1 - blockIdx.x;     // heavy tiles first
    const int bh = blockIdx.y;
    const int qb = qt * 128;

    const size_t hoff = (size_t)bh * T_SEQ * D_HEAD;
    const __nv_bfloat16* Qh = Qhi + hoff + (size_t)qb * D_HEAD;
    const __nv_bfloat16* Ql = Qlo + hoff + (size_t)qb * D_HEAD;
    const __nv_bfloat16* Kh = Khi + hoff;
    const __nv_bfloat16* Kl = Klo + hoff;
    const __nv_bfloat16* Vh = Vhi + hoff;
    const __nv_bfloat16* Vl = Vlo + hoff;

    // ---- stage Q (hi at sb, lo at sb+128*FPITCH) and extract A fragments ----
#pragma unroll
    for (int j = 0; j < 8; ++j) {
        int idx = tid + j * 256;               // 2048 chunks
        int tile = idx >> 10;
        int r = (idx >> 3) & 127;
        int c = idx & 7;
        uint32_t dst = sb + (uint32_t)tile * (128u * FPITCH) + (uint32_t)r * FPITCH + c * 16;
        const __nv_bfloat16* src = (tile == 0 ? Qh : Ql);
        CP_ASYNC16(dst, src + (size_t)r * D_HEAD + c * 8);
    }
    CP_COMMIT();
    CP_WAIT0();
    __syncthreads();

    uint32_t qhf[4][4], qlf[4][4];
    {
        uint32_t arow = (uint32_t)(w * 16 + (lane & 7) + ((lane & 8) ? 8 : 0));
        uint32_t acol = (uint32_t)(((lane & 16) ? 16 : 0));
#pragma unroll
        for (int kk = 0; kk < 4; ++kk) {
            uint32_t a = sb + arow * FPITCH + kk * 32 + acol;
            ldsm_x4(qhf[kk], a);
            ldsm_x4(qlf[kk], a + 128u * FPITCH);
        }
    }
    __syncthreads();   // Q fragments extracted; smem reusable

    float o[8][4];
#pragma unroll
    for (int j = 0; j < 8; ++j)
#pragma unroll
        for (int c = 0; c < 4; ++c) o[j][c] = 0.f;
    float m0 = -1e30f, m1 = -1e30f, l0 = 0.f, l1 = 0.f;

    const int ntiles = 2 * qt + 2;
    const int wqmin = qb + w * 16;
    const int wqmax = wqmin + 15;

    flash_load_stage(sb, 0, Kh, Kl, Vh, Vl, tid);
    CP_COMMIT();
    flash_load_stage(sb + FSTAGE, 64, Kh, Kl, Vh, Vl, tid);
    CP_COMMIT();

    for (int kt = 0; kt < ntiles; ++kt) {
        CP_WAIT1();
        __syncthreads();
        const uint32_t stage = sb + (uint32_t)(kt & 1) * FSTAGE;
        const int kb = kt * 64;

        if (kb <= wqmax) {
            // ---- S = Q K^T (3-pass hi/lo) ----
            float s[8][4];
#pragma unroll
            for (int j = 0; j < 8; ++j)
#pragma unroll
                for (int c = 0; c < 4; ++c) s[j][c] = 0.f;

            const uint32_t br = (uint32_t)((lane & 7) + ((lane & 16) ? 8 : 0));
            const uint32_t bc = (uint32_t)((lane & 8) ? 16 : 0);
#pragma unroll
            for (int kg = 0; kg < 4; ++kg) {
                uint32_t rowa = (uint32_t)(kg * 16) + br;
#pragma unroll
                for (int kk = 0; kk < 4; ++kk) {
                    uint32_t addr = stage + rowa * FPITCH + kk * 32 + bc;
                    uint32_t kh4[4], kl4[4];
                    ldsm_x4(kh4, addr);
                    ldsm_x4(kl4, addr + FTILE);
                    mma_bf16(s[2 * kg],     qhf[kk], &kh4[0]);
                    mma_bf16(s[2 * kg + 1], qhf[kk], &kh4[2]);
                    mma_bf16(s[2 * kg],     qlf[kk], &kh4[0]);
                    mma_bf16(s[2 * kg + 1], qlf[kk], &kh4[2]);
                    mma_bf16(s[2 * kg],     qhf[kk], &kl4[0]);
                    mma_bf16(s[2 * kg + 1], qhf[kk], &kl4[2]);
                }
            }

            // ---- causal mask ----
            if (kb + 63 > wqmin) {
                int r0 = wqmin + (lane >> 2), r1 = r0 + 8;
#pragma unroll
                for (int j = 0; j < 8; ++j) {
                    int k0 = kb + j * 8 + ((lane & 3) << 1);
                    if (k0 > r0)     s[j][0] = -1e30f;
                    if (k0 + 1 > r0) s[j][1] = -1e30f;
                    if (k0 > r1)     s[j][2] = -1e30f;
                    if (k0 + 1 > r1) s[j][3] = -1e30f;
                }
            }

            // ---- online softmax ----
            float mx0 = -1e30f, mx1 = -1e30f;
#pragma unroll
            for (int j = 0; j < 8; ++j) {
                mx0 = fmaxf(mx0, fmaxf(s[j][0], s[j][1]));
                mx1 = fmaxf(mx1, fmaxf(s[j][2], s[j][3]));
            }
            mx0 = fmaxf(mx0, __shfl_xor_sync(0xffffffffu, mx0, 1));
            mx0 = fmaxf(mx0, __shfl_xor_sync(0xffffffffu, mx0, 2));
            mx1 = fmaxf(mx1, __shfl_xor_sync(0xffffffffu, mx1, 1));
            mx1 = fmaxf(mx1, __shfl_xor_sync(0xffffffffu, mx1, 2));
            float m0n = fmaxf(m0, mx0), m1n = fmaxf(m1, mx1);
            float sc0 = __expf(m0 - m0n), sc1 = __expf(m1 - m1n);
            float rs0 = 0.f, rs1 = 0.f;
#pragma unroll
            for (int j = 0; j < 8; ++j) {
                s[j][0] = __expf(s[j][0] - m0n);
                s[j][1] = __expf(s[j][1] - m0n);
                s[j][2] = __expf(s[j][2] - m1n);
                s[j][3] = __expf(s[j][3] - m1n);
                rs0 += s[j][0] + s[j][1];
                rs1 += s[j][2] + s[j][3];
            }
            rs0 += __shfl_xor_sync(0xffffffffu, rs0, 1);
            rs0 += __shfl_xor_sync(0xffffffffu, rs0, 2);
            rs1 += __shfl_xor_sync(0xffffffffu, rs1, 1);
            rs1 += __shfl_xor_sync(0xffffffffu, rs1, 2);
            l0 = l0 * sc0 + rs0;
            l1 = l1 * sc1 + rs1;
            m0 = m0n; m1 = m1n;
#pragma unroll
            for (int j = 0; j < 8; ++j) {
                o[j][0] *= sc0; o[j][1] *= sc0;
                o[j][2] *= sc1; o[j][3] *= sc1;
            }

            // ---- pack P hi/lo A-fragments ----
            uint32_t aph[4][4], apl[4][4];
#pragma unroll
            for (int kk2 = 0; kk2 < 4; ++kk2) {
                int j0 = 2 * kk2, j1 = j0 + 1;
                pack_hl(s[j0][0], s[j0][1], aph[kk2][0], apl[kk2][0]);
                pack_hl(s[j0][2], s[j0][3], aph[kk2][1], apl[kk2][1]);
                pack_hl(s[j1][0], s[j1][1], aph[kk2][2], apl[kk2][2]);
                pack_hl(s[j1][2], s[j1][3], aph[kk2][3], apl[kk2][3]);
            }

            // ---- O += P V (3-pass) via ldmatrix.trans on V ----
            const uint32_t vr = (uint32_t)((lane & 7) + ((lane & 8) ? 8 : 0));
            const uint32_t vc = (uint32_t)((lane & 16) ? 16 : 0);
#pragma unroll
            for (int dg = 0; dg < 4; ++dg) {
#pragma unroll
                for (int kk2 = 0; kk2 < 4; ++kk2) {
                    uint32_t addr = stage + 2 * FTILE +
                                    (uint32_t)(kk2 * 16 + vr) * FPITCH + dg * 32 + vc;
                    uint32_t vh4[4], vl4[4];
                    ldsm_x4t(vh4, addr);
                    ldsm_x4t(vl4, addr + FTILE);
                    mma_bf16(o[2 * dg],     aph[kk2], &vh4[0]);
                    mma_bf16(o[2 * dg + 1], aph[kk2], &vh4[2]);
                    mma_bf16(o[2 * dg],     apl[kk2], &vh4[0]);
                    mma_bf16(o[2 * dg + 1], apl[kk2], &vh4[2]);
                    mma_bf16(o[2 * dg],     aph[kk2], &vl4[0]);
                    mma_bf16(o[2 * dg + 1], aph[kk2], &vl4[2]);
                }
            }
        }

        __syncthreads();
        if (kt + 2 < ntiles)
            flash_load_stage(sb + (uint32_t)(kt & 1) * FSTAGE, (kt + 2) * 64,
                             Kh, Kl, Vh, Vl, tid);
        CP_COMMIT();
    }

    // ---- normalize and write fp16 hi/lo (proj GEMM A-operand) ----
    const float inv0 = 1.0f / l0, inv1 = 1.0f / l1;
    const int b = bh >> 4, h = bh & 15;
    const int r0 = qb + w * 16 + (lane >> 2);
#pragma unroll
    for (int j = 0; j < 8; ++j) {
        int col = h * 64 + j * 8 + (lane & 3) * 2;
        float v00 = o[j][0] * inv0, v01 = o[j][1] * inv0;
        float v10 = o[j][2] * inv1, v11 = o[j][3] * inv1;
        __half h00 = __float2half_rn(v00), h01 = __float2half_rn(v01);
        __half h10 = __float2half_rn(v10), h11 = __float2half_rn(v11);
        __half2 hh0 = {h00, h01}, hh1 = {h10, h11};
        __half2 ll0 = {__float2half_rn(v00 - __half2float(h00)),
                       __float2half_rn(v01 - __half2float(h01))};
        __half2 ll1 = {__float2half_rn(v10 - __half2float(h10)),
                       __float2half_rn(v11 - __half2float(h11))};
        size_t base0 = (size_t)(b * T_SEQ + r0) * C_DIM + col;
        size_t base1 = (size_t)(b * T_SEQ + r0 + 8) * C_DIM + col;
        *(__half2*)&yhi[base0] = hh0;
        *(__half2*)&yhi[base1] = hh1;
        *(__half2*)&ylo[base0] = ll0;
        *(__half2*)&ylo[base1] = ll1;
    }
}

// ---------------------------------------------------------------------------
extern "C" void kernel_launch(void* const* d_in, const int* in_sizes, int n_in,
                              void* d_out, int out_size)
{
    const float* x      = (const float*)d_in[0];
    const float* w_attn = (const float*)d_in[1];
    const float* w_proj = (const float*)d_in[2];
    float* out = (float*)d_out;

    float *qkv;
    __half *xhi, *xlo, *wa, *wp, *yhi, *ylo;
    __nv_bfloat16 *Qhi, *Qlo, *Khi, *Klo, *Vhi, *Vlo;
    cudaGetSymbolAddress((void**)&qkv, g_qkv);
    cudaGetSymbolAddress((void**)&xhi, g_xhi);
    cudaGetSymbolAddress((void**)&xlo, g_xlo);
    cudaGetSymbolAddress((void**)&wa, g_wa);
    cudaGetSymbolAddress((void**)&wp, g_wp);
    cudaGetSymbolAddress((void**)&yhi, g_yhi);
    cudaGetSymbolAddress((void**)&ylo, g_ylo);
    cudaGetSymbolAddress((void**)&Qhi, g_Qhi);
    cudaGetSymbolAddress((void**)&Qlo, g_Qlo);
    cudaGetSymbolAddress((void**)&Khi, g_Khi);
    cudaGetSymbolAddress((void**)&Klo, g_Klo);
    cudaGetSymbolAddress((void**)&Vhi, g_Vhi);
    cudaGetSymbolAddress((void**)&Vlo, g_Vlo);

    static bool attr_set = false;
    if (!attr_set) {
        cudaFuncSetAttribute(gemm_f16_kernel,
                             cudaFuncAttributeMaxDynamicSharedMemorySize, GEMM_SMEM);
        cudaFuncSetAttribute(flash_mma_kernel,
                             cudaFuncAttributeMaxDynamicSharedMemorySize, FL_SMEM);
        attr_set = true;
    }

    // input splits / conversions
    {
        int n4 = M_ROWS * C_DIM / 4;
        split_f16_kernel<<<(n4 + 255) / 256, 256>>>(x, xhi, xlo, n4);
        n4 = QKV_COLS * C_DIM / 4;
        conv_f16_kernel<<<(n4 + 255) / 256, 256>>>(w_attn, wa, n4);
        n4 = C_DIM * C_DIM / 4;
        conv_f16_kernel<<<(n4 + 255) / 256, 256>>>(w_proj, wp, n4);
    }
    // 1) qkv = x @ w_attn^T   (fp16 2-pass HMMA)
    {
        dim3 grid(QKV_COLS / 128, M_ROWS / 128);
        gemm_f16_kernel<<<grid, 256, GEMM_SMEM>>>(xhi, xlo, wa, qkv,
                                                  QKV_COLS, C_DIM);
    }
    // 2) RoPE + split + relayout
    {
        int total = B_DIM * T_SEQ * H_DIM * 32;
        rope_split_kernel<<<total / 256, 256>>>(qkv, Qhi, Qlo, Khi, Klo, Vhi, Vlo);
    }
    // 3) flash attention (tensor cores) -> yhi/ylo fp16
    {
        dim3 grid(T_SEQ / 128, B_DIM * H_DIM);
        flash_mma_kernel<<<grid, 256, FL_SMEM>>>(Qhi, Qlo, Khi, Klo, Vhi, Vlo,
                                                 yhi, ylo);
    }
    // 4) out = y @ w_proj^T   (fp16 2-pass HMMA)
    {
        dim3 grid(C_DIM / 128, M_ROWS / 128);
        gemm_f16_kernel<<<grid, 256, GEMM_SMEM>>>(yhi, ylo, wp, out,
                                                  C_DIM, C_DIM);
    }
}

// round 7
// speedup vs baseline: 1.8157x; 1.4529x over previous
#include <cuda_runtime.h>
#include <cuda_bf16.h>
#include <cuda_fp16.h>
#include <cstdint>
#include <math.h>

#define B_DIM 2
#define T_SEQ 2048
#define C_DIM 1024
#define H_DIM 16
#define D_HEAD 64
#define M_ROWS (B_DIM * T_SEQ)       // 4096
#define QKV_COLS (3 * C_DIM)         // 3072

// ---------------------------------------------------------------------------
// Scratch (allocation-free rule: __device__ globals)
// ---------------------------------------------------------------------------
__device__ float g_qkv[(size_t)M_ROWS * QKV_COLS];   // (B,T,3,H,D)

__device__ __half g_x16[(size_t)M_ROWS * C_DIM];     // x fp16
__device__ __half g_wa [(size_t)QKV_COLS * C_DIM];   // w_attn fp16
__device__ __half g_wp [(size_t)C_DIM * C_DIM];      // w_proj fp16
__device__ __half g_yh [(size_t)M_ROWS * C_DIM];     // attention out fp16

// head-major fp16 Q(hi/lo), K, V: (B,H,T,D)
#define HD_ELEMS ((size_t)B_DIM * H_DIM * T_SEQ * D_HEAD)
__device__ __half g_Qhi[HD_ELEMS];
__device__ __half g_Qlo[HD_ELEMS];
__device__ __half g_Kh [HD_ELEMS];
__device__ __half g_Vh [HD_ELEMS];

// ---------------------------------------------------------------------------
// helpers
// ---------------------------------------------------------------------------
__device__ __forceinline__ uint32_t smem_to_u32(const void* smem_ptr) {
    uint32_t addr;
    asm("{ .reg .u64 tmp; cvta.to.shared.u64 tmp, %1; cvt.u32.u64 %0, tmp; }"
        : "=r"(addr) : "l"(smem_ptr));
    return addr;
}

#define CP_ASYNC16(dst_u32, src_ptr) \
    asm volatile("cp.async.cg.shared.global [%0], [%1], 16;" \
        :: "r"(dst_u32), "l"(__cvta_generic_to_global(src_ptr)))
#define CP_COMMIT() asm volatile("cp.async.commit_group;")
#define CP_WAIT1()  asm volatile("cp.async.wait_group 1;")
#define CP_WAIT0()  asm volatile("cp.async.wait_group 0;")

__device__ __forceinline__ void ldsm_x4(uint32_t* r, uint32_t addr) {
    asm volatile("ldmatrix.sync.aligned.m8n8.x4.shared.b16 {%0,%1,%2,%3}, [%4];"
        : "=r"(r[0]), "=r"(r[1]), "=r"(r[2]), "=r"(r[3]) : "r"(addr));
}
__device__ __forceinline__ void ldsm_x4t(uint32_t* r, uint32_t addr) {
    asm volatile("ldmatrix.sync.aligned.m8n8.x4.trans.shared.b16 {%0,%1,%2,%3}, [%4];"
        : "=r"(r[0]), "=r"(r[1]), "=r"(r[2]), "=r"(r[3]) : "r"(addr));
}
__device__ __forceinline__ void mma_f16(float* d, const uint32_t* a, const uint32_t* b) {
    asm volatile(
        "mma.sync.aligned.m16n8k16.row.col.f32.f16.f16.f32 "
        "{%0,%1,%2,%3}, {%4,%5,%6,%7}, {%8,%9}, {%0,%1,%2,%3};"
        : "+f"(d[0]), "+f"(d[1]), "+f"(d[2]), "+f"(d[3])
        : "r"(a[0]), "r"(a[1]), "r"(a[2]), "r"(a[3]), "r"(b[0]), "r"(b[1]));
}

__device__ __forceinline__ void pack_hl_f16(float a, float b, uint32_t& hi, uint32_t& lo) {
    __half2 h = __floats2half2_rn(a, b);
    float ra = a - __half2float(h.x);
    float rb = b - __half2float(h.y);
    __half2 l = __floats2half2_rn(ra, rb);
    hi = *(uint32_t*)&h;
    lo = *(uint32_t*)&l;
}

// ---------------------------------------------------------------------------
// fp32 -> fp16 convert
// ---------------------------------------------------------------------------
__global__ void conv_f16_kernel(const float* __restrict__ x,
                                __half* __restrict__ hi, int n4)
{
    int i = blockIdx.x * blockDim.x + threadIdx.x;
    if (i >= n4) return;
    float4 v = ((const float4*)x)[i];
    __half2 hp0 = __floats2half2_rn(v.x, v.y);
    __half2 hp1 = __floats2half2_rn(v.z, v.w);
    ((__half2*)hi)[2 * i]     = hp0;
    ((__half2*)hi)[2 * i + 1] = hp1;
}

// ---------------------------------------------------------------------------
// Tensor-core GEMM NT via mma.sync fp16, single pass:
//   C[M,N] = A[M,K] * B[N,K]^T
// 128x128 CTA tile, BK=32, 256 threads (8 warps 2x4, 64x32 warp tiles),
// cp.async double buffer, 80B smem pitch.
// ---------------------------------------------------------------------------
#define GTILE 10240u                  // 128 rows * 80B
#define GSTAGE (2 * GTILE)            // A, B
#define GEMM_SMEM (2 * GSTAGE)        // 40960 B

__device__ __forceinline__ void gemm_load_stage(
    uint32_t sdst,
    const __half* __restrict__ A, const __half* __restrict__ B,
    int bm, int bn, int K, int k0, int tid)
{
#pragma unroll
    for (int i = 0; i < 2; ++i) {
        int idx = tid + i * 256;           // 0..511 -> (row, 16B-chunk)
        int r = idx >> 2, c = idx & 3;
        uint32_t so = (uint32_t)(r * 80 + c * 16);
        size_t ga = (size_t)(bm + r) * K + k0 + c * 8;
        size_t gb = (size_t)(bn + r) * K + k0 + c * 8;
        CP_ASYNC16(sdst + so,         A + ga);
        CP_ASYNC16(sdst + GTILE + so, B + gb);
    }
}

__global__ void __launch_bounds__(256) gemm_f16_kernel(
    const __half* __restrict__ A, const __half* __restrict__ B,
    float* __restrict__ C, int N, int K)
{
    extern __shared__ char smem[];
    const uint32_t sb = smem_to_u32(smem);
    const int tid = threadIdx.x;
    const int lane = tid & 31, wid = tid >> 5;
    const int wr = wid >> 2, wc = wid & 3;          // warp grid 2x4
    const int bm = blockIdx.y * 128, bn = blockIdx.x * 128;

    float acc[4][4][4];
#pragma unroll
    for (int mi = 0; mi < 4; ++mi)
#pragma unroll
        for (int ni = 0; ni < 4; ++ni)
#pragma unroll
            for (int j = 0; j < 4; ++j) acc[mi][ni][j] = 0.f;

    const int nk = K >> 5;
    gemm_load_stage(sb, A, B, bm, bn, K, 0, tid);
    CP_COMMIT();
    gemm_load_stage(sb + GSTAGE, A, B, bm, bn, K, 32, tid);
    CP_COMMIT();

    for (int ks = 0; ks < nk; ++ks) {
        CP_WAIT1();
        __syncthreads();
        const uint32_t sA = sb + (uint32_t)(ks & 1) * GSTAGE;
        const uint32_t sB = sA + GTILE;

#pragma unroll
        for (int kk = 0; kk < 2; ++kk) {
            const uint32_t colo = (uint32_t)(kk * 32 + (lane >> 4) * 16);
            uint32_t af[4][4], bf[4][2];
#pragma unroll
            for (int mi = 0; mi < 4; ++mi) {
                uint32_t ro = (uint32_t)(wr * 64 + mi * 16 + (lane & 15)) * 80 + colo;
                ldsm_x4(af[mi], sA + ro);
            }
#pragma unroll
            for (int nj = 0; nj < 2; ++nj) {
                uint32_t ro = (uint32_t)(wc * 32 + nj * 16 + (lane & 15)) * 80 + colo;
                uint32_t t[4];
                ldsm_x4(t, sB + ro);
                bf[nj * 2][0] = t[0]; bf[nj * 2][1] = t[2];
                bf[nj * 2 + 1][0] = t[1]; bf[nj * 2 + 1][1] = t[3];
            }
#pragma unroll
            for (int mi = 0; mi < 4; ++mi)
#pragma unroll
                for (int ni = 0; ni < 4; ++ni)
                    mma_f16(acc[mi][ni], af[mi], bf[ni]);
        }

        __syncthreads();
        if (ks + 2 < nk)
            gemm_load_stage(sb + (uint32_t)(ks & 1) * GSTAGE, A, B,
                            bm, bn, K, (ks + 2) * 32, tid);
        CP_COMMIT();
    }

    // epilogue: direct fragment stores
#pragma unroll
    for (int mi = 0; mi < 4; ++mi) {
        int row = bm + wr * 64 + mi * 16 + (lane >> 2);
#pragma unroll
        for (int ni = 0; ni < 4; ++ni) {
            int col = bn + wc * 32 + ni * 8 + (lane & 3) * 2;
            float2 v0 = make_float2(acc[mi][ni][0], acc[mi][ni][1]);
            float2 v1 = make_float2(acc[mi][ni][2], acc[mi][ni][3]);
            *(float2*)&C[(size_t)row * N + col] = v0;
            *(float2*)&C[(size_t)(row + 8) * N + col] = v1;
        }
    }
}

// ---------------------------------------------------------------------------
// Prep: RoPE (q,k) + fp32->fp16 + head-major relayout (B,H,T,D).
// Q gets hi/lo split (compensated S pass); K,V plain fp16.
// ---------------------------------------------------------------------------
__global__ void rope_split_kernel(const float* __restrict__ qkv,
                                  __half* __restrict__ Qhi, __half* __restrict__ Qlo,
                                  __half* __restrict__ Kh, __half* __restrict__ Vh)
{
    int idx = blockIdx.x * blockDim.x + threadIdx.x;
    int i = idx & 31;
    int h = (idx >> 5) & 15;
    int t = (idx >> 9) & 2047;
    int b = idx >> 20;

    float p = powf(10000.0f, (float)(2 * i) * (1.0f / 64.0f));
    float ang = (float)t * (1.0f / p);
    float sn, cs;
    sincosf(ang, &sn, &cs);

    size_t src = ((size_t)(b * T_SEQ + t)) * QKV_COLS + h * D_HEAD;
    size_t dst = ((size_t)((b * H_DIM + h) * T_SEQ + t)) * D_HEAD;

    // q (fold 1/8 scale), hi/lo
    {
        float q1 = qkv[src + i], q2 = qkv[src + i + 32];
        float a = (q1 * cs + q2 * sn) * 0.125f;
        float c2 = (-q1 * sn + q2 * cs) * 0.125f;
        __half ha = __float2half_rn(a), hc = __float2half_rn(c2);
        Qhi[dst + i] = ha; Qhi[dst + i + 32] = hc;
        Qlo[dst + i] = __float2half_rn(a - __half2float(ha));
        Qlo[dst + i + 32] = __float2half_rn(c2 - __half2float(hc));
    }
    // k (plain fp16)
    {
        float k1 = qkv[src + C_DIM + i], k2 = qkv[src + C_DIM + i + 32];
        Kh[dst + i]      = __float2half_rn(k1 * cs + k2 * sn);
        Kh[dst + i + 32] = __float2half_rn(-k1 * sn + k2 * cs);
    }
    // v (plain fp16)
    {
        Vh[dst + i]      = __float2half_rn(qkv[src + 2 * C_DIM + i]);
        Vh[dst + i + 32] = __float2half_rn(qkv[src + 2 * C_DIM + i + 32]);
    }
}

// ---------------------------------------------------------------------------
// Flash attention via mma.sync fp16, causal.
// CTA: 128 queries x one (b,h); 8 warps x 16 rows. 64-key tiles, double buffer.
// S: 2-pass (Qhi,Qlo) x K.  PV: 2-pass (Phi,Plo) x V.
// ---------------------------------------------------------------------------
#define FPITCH 144u
#define FTILE  (64u * FPITCH)          // 9216
#define FSTAGE (2u * FTILE)            // Kh, Vh = 18432
#define FL_SMEM (2u * FSTAGE)          // 36864 (also covers Q staging)

__device__ __forceinline__ void flash_load_stage(
    uint32_t dstbase, int kb,
    const __half* __restrict__ Kh, const __half* __restrict__ Vh, int tid)
{
    // 1024 16B-chunks: 2 tiles * 64 rows * 8 chunks
#pragma unroll
    for (int j = 0; j < 4; ++j) {
        int idx = tid + j * 256;
        int tile = idx >> 9;                   // 0..1
        int r = (idx >> 3) & 63;
        int c = idx & 7;
        uint32_t dst = dstbase + (uint32_t)tile * FTILE + (uint32_t)r * FPITCH + c * 16;
        const __half* src = (tile == 0 ? Kh : Vh);
        CP_ASYNC16(dst, src + (size_t)(kb + r) * D_HEAD + c * 8);
    }
}

__global__ void __launch_bounds__(256) flash_mma_kernel(
    const __half* __restrict__ Qhi, const __half* __restrict__ Qlo,
    const __half* __restrict__ Khg, const __half* __restrict__ Vhg,
    __half* __restrict__ yh)
{
    extern __shared__ char fsm[];
    const uint32_t sb = smem_to_u32(fsm);
    const int tid = threadIdx.x;
    const int lane = tid & 31, w = tid >> 5;
    const int qt = gridDim.x - 1 - blockIdx.x;     // heavy tiles first
    const int bh = blockIdx.y;
    const int qb = qt * 128;

    const size_t hoff = (size_t)bh * T_SEQ * D_HEAD;
    const __half* Qh = Qhi + hoff + (size_t)qb * D_HEAD;
    const __half* Ql = Qlo + hoff + (size_t)qb * D_HEAD;
    const __half* Kh = Khg + hoff;
    const __half* Vh = Vhg + hoff;

    // ---- stage Q (hi at sb, lo at sb+128*FPITCH), extract A fragments ----
#pragma unroll
    for (int j = 0; j < 8; ++j) {
        int idx = tid + j * 256;               // 2048 chunks
        int tile = idx >> 10;
        int r = (idx >> 3) & 127;
        int c = idx & 7;
        uint32_t dst = sb + (uint32_t)tile * (128u * FPITCH) + (uint32_t)r * FPITCH + c * 16;
        const __half* src = (tile == 0 ? Qh : Ql);
        CP_ASYNC16(dst, src + (size_t)r * D_HEAD + c * 8);
    }
    CP_COMMIT();
    CP_WAIT0();
    __syncthreads();

    uint32_t qhf[4][4], qlf[4][4];
    {
        uint32_t arow = (uint32_t)(w * 16 + (lane & 7) + ((lane & 8) ? 8 : 0));
        uint32_t acol = (uint32_t)(((lane & 16) ? 16 : 0));
#pragma unroll
        for (int kk = 0; kk < 4; ++kk) {
            uint32_t a = sb + arow * FPITCH + kk * 32 + acol;
            ldsm_x4(qhf[kk], a);
            ldsm_x4(qlf[kk], a + 128u * FPITCH);
        }
    }
    __syncthreads();   // Q fragments extracted; smem reusable

    float o[8][4];
#pragma unroll
    for (int j = 0; j < 8; ++j)
#pragma unroll
        for (int c = 0; c < 4; ++c) o[j][c] = 0.f;
    float m0 = -1e30f, m1 = -1e30f, l0 = 0.f, l1 = 0.f;

    const int ntiles = 2 * qt + 2;
    const int wqmin = qb + w * 16;
    const int wqmax = wqmin + 15;

    flash_load_stage(sb, 0, Kh, Vh, tid);
    CP_COMMIT();
    flash_load_stage(sb + FSTAGE, 64, Kh, Vh, tid);
    CP_COMMIT();

    for (int kt = 0; kt < ntiles; ++kt) {
        CP_WAIT1();
        __syncthreads();
        const uint32_t stage = sb + (uint32_t)(kt & 1) * FSTAGE;
        const int kb = kt * 64;

        if (kb <= wqmax) {
            // ---- S = Q K^T (2-pass Q hi/lo) ----
            float s[8][4];
#pragma unroll
            for (int j = 0; j < 8; ++j)
#pragma unroll
                for (int c = 0; c < 4; ++c) s[j][c] = 0.f;

            const uint32_t br = (uint32_t)((lane & 7) + ((lane & 16) ? 8 : 0));
            const uint32_t bc = (uint32_t)((lane & 8) ? 16 : 0);
#pragma unroll
            for (int kg = 0; kg < 4; ++kg) {
                uint32_t rowa = (uint32_t)(kg * 16) + br;
#pragma unroll
                for (int kk = 0; kk < 4; ++kk) {
                    uint32_t addr = stage + rowa * FPITCH + kk * 32 + bc;
                    uint32_t k4[4];
                    ldsm_x4(k4, addr);
                    mma_f16(s[2 * kg],     qhf[kk], &k4[0]);
                    mma_f16(s[2 * kg + 1], qhf[kk], &k4[2]);
                    mma_f16(s[2 * kg],     qlf[kk], &k4[0]);
                    mma_f16(s[2 * kg + 1], qlf[kk], &k4[2]);
                }
            }

            // ---- causal mask ----
            if (kb + 63 > wqmin) {
                int r0 = wqmin + (lane >> 2), r1 = r0 + 8;
#pragma unroll
                for (int j = 0; j < 8; ++j) {
                    int k0 = kb + j * 8 + ((lane & 3) << 1);
                    if (k0 > r0)     s[j][0] = -1e30f;
                    if (k0 + 1 > r0) s[j][1] = -1e30f;
                    if (k0 > r1)     s[j][2] = -1e30f;
                    if (k0 + 1 > r1) s[j][3] = -1e30f;
                }
            }

            // ---- online softmax ----
            float mx0 = -1e30f, mx1 = -1e30f;
#pragma unroll
            for (int j = 0; j < 8; ++j) {
                mx0 = fmaxf(mx0, fmaxf(s[j][0], s[j][1]));
                mx1 = fmaxf(mx1, fmaxf(s[j][2], s[j][3]));
            }
            mx0 = fmaxf(mx0, __shfl_xor_sync(0xffffffffu, mx0, 1));
            mx0 = fmaxf(mx0, __shfl_xor_sync(0xffffffffu, mx0, 2));
            mx1 = fmaxf(mx1, __shfl_xor_sync(0xffffffffu, mx1, 1));
            mx1 = fmaxf(mx1, __shfl_xor_sync(0xffffffffu, mx1, 2));
            float m0n = fmaxf(m0, mx0), m1n = fmaxf(m1, mx1);
            float sc0 = __expf(m0 - m0n), sc1 = __expf(m1 - m1n);
            float rs0 = 0.f, rs1 = 0.f;
#pragma unroll
            for (int j = 0; j < 8; ++j) {
                s[j][0] = __expf(s[j][0] - m0n);
                s[j][1] = __expf(s[j][1] - m0n);
                s[j][2] = __expf(s[j][2] - m1n);
                s[j][3] = __expf(s[j][3] - m1n);
                rs0 += s[j][0] + s[j][1];
                rs1 += s[j][2] + s[j][3];
            }
            rs0 += __shfl_xor_sync(0xffffffffu, rs0, 1);
            rs0 += __shfl_xor_sync(0xffffffffu, rs0, 2);
            rs1 += __shfl_xor_sync(0xffffffffu, rs1, 1);
            rs1 += __shfl_xor_sync(0xffffffffu, rs1, 2);
            l0 = l0 * sc0 + rs0;
            l1 = l1 * sc1 + rs1;
            m0 = m0n; m1 = m1n;
#pragma unroll
            for (int j = 0; j < 8; ++j) {
                o[j][0] *= sc0; o[j][1] *= sc0;
                o[j][2] *= sc1; o[j][3] *= sc1;
            }

            // ---- pack P hi/lo A-fragments (fp16) ----
            uint32_t aph[4][4], apl[4][4];
#pragma unroll
            for (int kk2 = 0; kk2 < 4; ++kk2) {
                int j0 = 2 * kk2, j1 = j0 + 1;
                pack_hl_f16(s[j0][0], s[j0][1], aph[kk2][0], apl[kk2][0]);
                pack_hl_f16(s[j0][2], s[j0][3], aph[kk2][1], apl[kk2][1]);
                pack_hl_f16(s[j1][0], s[j1][1], aph[kk2][2], apl[kk2][2]);
                pack_hl_f16(s[j1][2], s[j1][3], aph[kk2][3], apl[kk2][3]);
            }

            // ---- O += P V (2-pass P hi/lo) via ldmatrix.trans on V ----
            const uint32_t vr = (uint32_t)((lane & 7) + ((lane & 8) ? 8 : 0));
            const uint32_t vc = (uint32_t)((lane & 16) ? 16 : 0);
#pragma unroll
            for (int dg = 0; dg < 4; ++dg) {
#pragma unroll
                for (int kk2 = 0; kk2 < 4; ++kk2) {
                    uint32_t addr = stage + FTILE +
                                    (uint32_t)(kk2 * 16 + vr) * FPITCH + dg * 32 + vc;
                    uint32_t v4[4];
                    ldsm_x4t(v4, addr);
                    mma_f16(o[2 * dg],     aph[kk2], &v4[0]);
                    mma_f16(o[2 * dg + 1], aph[kk2], &v4[2]);
                    mma_f16(o[2 * dg],     apl[kk2], &v4[0]);
                    mma_f16(o[2 * dg + 1], apl[kk2], &v4[2]);
                }
            }
        }

        __syncthreads();
        if (kt + 2 < ntiles)
            flash_load_stage(sb + (uint32_t)(kt & 1) * FSTAGE, (kt + 2) * 64,
                             Kh, Vh, tid);
        CP_COMMIT();
    }

    // ---- normalize and write fp16 (proj GEMM A-operand) ----
    const float inv0 = 1.0f / l0, inv1 = 1.0f / l1;
    const int b = bh >> 4, h = bh & 15;
    const int r0 = qb + w * 16 + (lane >> 2);
#pragma unroll
    for (int j = 0; j < 8; ++j) {
        int col = h * 64 + j * 8 + (lane & 3) * 2;
        __half2 hh0 = __floats2half2_rn(o[j][0] * inv0, o[j][1] * inv0);
        __half2 hh1 = __floats2half2_rn(o[j][2] * inv1, o[j][3] * inv1);
        *(__half2*)&yh[(size_t)(b * T_SEQ + r0) * C_DIM + col] = hh0;
        *(__half2*)&yh[(size_t)(b * T_SEQ + r0 + 8) * C_DIM + col] = hh1;
    }
}

// ---------------------------------------------------------------------------
extern "C" void kernel_launch(void* const* d_in, const int* in_sizes, int n_in,
                              void* d_out, int out_size)
{
    const float* x      = (const float*)d_in[0];
    const float* w_attn = (const float*)d_in[1];
    const float* w_proj = (const float*)d_in[2];
    float* out = (float*)d_out;

    float *qkv;
    __half *x16, *wa, *wp, *yh;
    __half *Qhi, *Qlo, *Kh, *Vh;
    cudaGetSymbolAddress((void**)&qkv, g_qkv);
    cudaGetSymbolAddress((void**)&x16, g_x16);
    cudaGetSymbolAddress((void**)&wa, g_wa);
    cudaGetSymbolAddress((void**)&wp, g_wp);
    cudaGetSymbolAddress((void**)&yh, g_yh);
    cudaGetSymbolAddress((void**)&Qhi, g_Qhi);
    cudaGetSymbolAddress((void**)&Qlo, g_Qlo);
    cudaGetSymbolAddress((void**)&Kh, g_Kh);
    cudaGetSymbolAddress((void**)&Vh, g_Vh);

    static bool attr_set = false;
    if (!attr_set) {
        cudaFuncSetAttribute(gemm_f16_kernel,
                             cudaFuncAttributeMaxDynamicSharedMemorySize, GEMM_SMEM);
        cudaFuncSetAttribute(flash_mma_kernel,
                             cudaFuncAttributeMaxDynamicSharedMemorySize, FL_SMEM);
        attr_set = true;
    }

    // input conversions
    {
        int n4 = M_ROWS * C_DIM / 4;
        conv_f16_kernel<<<(n4 + 255) / 256, 256>>>(x, x16, n4);
        n4 = QKV_COLS * C_DIM / 4;
        conv_f16_kernel<<<(n4 + 255) / 256, 256>>>(w_attn, wa, n4);
        n4 = C_DIM * C_DIM / 4;
        conv_f16_kernel<<<(n4 + 255) / 256, 256>>>(w_proj, wp, n4);
    }
    // 1) qkv = x @ w_attn^T   (fp16 single-pass HMMA)
    {
        dim3 grid(QKV_COLS / 128, M_ROWS / 128);
        gemm_f16_kernel<<<grid, 256, GEMM_SMEM>>>(x16, wa, qkv, QKV_COLS, C_DIM);
    }
    // 2) RoPE + fp16 + relayout
    {
        int total = B_DIM * T_SEQ * H_DIM * 32;
        rope_split_kernel<<<total / 256, 256>>>(qkv, Qhi, Qlo, Kh, Vh);
    }
    // 3) flash attention (tensor cores) -> yh fp16
    {
        dim3 grid(T_SEQ / 128, B_DIM * H_DIM);
        flash_mma_kernel<<<grid, 256, FL_SMEM>>>(Qhi, Qlo, Kh, Vh, yh);
    }
    // 4) out = y @ w_proj^T   (fp16 single-pass HMMA)
    {
        dim3 grid(C_DIM / 128, M_ROWS / 128);
        gemm_f16_kernel<<<grid, 256, GEMM_SMEM>>>(yh, wp, out, C_DIM, C_DIM);
    }
}

// round 8
// speedup vs baseline: 1.9813x; 1.0912x over previous
#include <cuda_runtime.h>
#include <cuda_bf16.h>
#include <cuda_fp16.h>
#include <cstdint>
#include <math.h>

#define B_DIM 2
#define T_SEQ 2048
#define C_DIM 1024
#define H_DIM 16
#define D_HEAD 64
#define M_ROWS (B_DIM * T_SEQ)       // 4096
#define QKV_COLS (3 * C_DIM)         // 3072

// ---------------------------------------------------------------------------
// Scratch (allocation-free rule: __device__ globals)
// ---------------------------------------------------------------------------
__device__ __half g_qkv16[(size_t)M_ROWS * QKV_COLS]; // qkv fp16 (B,T,3,H,D)

__device__ __half g_x16[(size_t)M_ROWS * C_DIM];     // x fp16
__device__ __half g_wa [(size_t)QKV_COLS * C_DIM];   // w_attn fp16
__device__ __half g_wp [(size_t)C_DIM * C_DIM];      // w_proj fp16
__device__ __half g_yh [(size_t)M_ROWS * C_DIM];     // attention out fp16

// head-major fp16 Q(hi/lo), K, V: (B,H,T,D)
#define HD_ELEMS ((size_t)B_DIM * H_DIM * T_SEQ * D_HEAD)
__device__ __half g_Qhi[HD_ELEMS];
__device__ __half g_Qlo[HD_ELEMS];
__device__ __half g_Kh [HD_ELEMS];
__device__ __half g_Vh [HD_ELEMS];

// ---------------------------------------------------------------------------
// helpers
// ---------------------------------------------------------------------------
__device__ __forceinline__ uint32_t smem_to_u32(const void* smem_ptr) {
    uint32_t addr;
    asm("{ .reg .u64 tmp; cvta.to.shared.u64 tmp, %1; cvt.u32.u64 %0, tmp; }"
        : "=r"(addr) : "l"(smem_ptr));
    return addr;
}

#define CP_ASYNC16(dst_u32, src_ptr) \
    asm volatile("cp.async.cg.shared.global [%0], [%1], 16;" \
        :: "r"(dst_u32), "l"(__cvta_generic_to_global(src_ptr)))
#define CP_COMMIT() asm volatile("cp.async.commit_group;")
#define CP_WAIT1()  asm volatile("cp.async.wait_group 1;")
#define CP_WAIT0()  asm volatile("cp.async.wait_group 0;")

__device__ __forceinline__ void ldsm_x4(uint32_t* r, uint32_t addr) {
    asm volatile("ldmatrix.sync.aligned.m8n8.x4.shared.b16 {%0,%1,%2,%3}, [%4];"
        : "=r"(r[0]), "=r"(r[1]), "=r"(r[2]), "=r"(r[3]) : "r"(addr));
}
__device__ __forceinline__ void ldsm_x4t(uint32_t* r, uint32_t addr) {
    asm volatile("ldmatrix.sync.aligned.m8n8.x4.trans.shared.b16 {%0,%1,%2,%3}, [%4];"
        : "=r"(r[0]), "=r"(r[1]), "=r"(r[2]), "=r"(r[3]) : "r"(addr));
}
__device__ __forceinline__ void mma_f16(float* d, const uint32_t* a, const uint32_t* b) {
    asm volatile(
        "mma.sync.aligned.m16n8k16.row.col.f32.f16.f16.f32 "
        "{%0,%1,%2,%3}, {%4,%5,%6,%7}, {%8,%9}, {%0,%1,%2,%3};"
        : "+f"(d[0]), "+f"(d[1]), "+f"(d[2]), "+f"(d[3])
        : "r"(a[0]), "r"(a[1]), "r"(a[2]), "r"(a[3]), "r"(b[0]), "r"(b[1]));
}

// ---------------------------------------------------------------------------
// fp32 -> fp16 convert
// ---------------------------------------------------------------------------
__global__ void conv_f16_kernel(const float* __restrict__ x,
                                __half* __restrict__ hi, int n4)
{
    int i = blockIdx.x * blockDim.x + threadIdx.x;
    if (i >= n4) return;
    float4 v = ((const float4*)x)[i];
    __half2 hp0 = __floats2half2_rn(v.x, v.y);
    __half2 hp1 = __floats2half2_rn(v.z, v.w);
    ((__half2*)hi)[2 * i]     = hp0;
    ((__half2*)hi)[2 * i + 1] = hp1;
}

// ---------------------------------------------------------------------------
// Tensor-core GEMM NT via mma.sync fp16, single pass:
//   C[M,N] = A[M,K] * B[N,K]^T
// 128x256 CTA tile, BK=32, 256 threads (8 warps 2x4, 64x64 warp tiles),
// cp.async double buffer, 80B smem pitch. Templated fp16/fp32 output.
// ---------------------------------------------------------------------------
#define GA_BYTES (128u * 80u)            // 10240
#define GB_BYTES (256u * 80u)            // 20480
#define GSTAGE   (GA_BYTES + GB_BYTES)   // 30720
#define GEMM_SMEM (2 * GSTAGE)           // 61440

__device__ __forceinline__ void gemm_load_stage(
    uint32_t sdst,
    const __half* __restrict__ A, const __half* __restrict__ B,
    int bm, int bn, int K, int k0, int tid)
{
#pragma unroll
    for (int i = 0; i < 6; ++i) {
        int idx = tid + i * 256;           // 0..1535
        if (idx < 512) {                   // A: 128 rows x 4 chunks
            int r = idx >> 2, c = idx & 3;
            CP_ASYNC16(sdst + (uint32_t)(r * 80 + c * 16),
                       A + (size_t)(bm + r) * K + k0 + c * 8);
        } else {                           // B: 256 rows x 4 chunks
            int j = idx - 512;
            int r = j >> 2, c = j & 3;
            CP_ASYNC16(sdst + GA_BYTES + (uint32_t)(r * 80 + c * 16),
                       B + (size_t)(bn + r) * K + k0 + c * 8);
        }
    }
}

template<bool HALF_OUT>
__global__ void __launch_bounds__(256) gemm_f16_kernel(
    const __half* __restrict__ A, const __half* __restrict__ B,
    void* __restrict__ Cv, int N, int K)
{
    extern __shared__ char smem[];
    const uint32_t sb = smem_to_u32(smem);
    const int tid = threadIdx.x;
    const int lane = tid & 31, wid = tid >> 5;
    const int wr = wid >> 2, wc = wid & 3;          // warp grid 2x4
    const int bm = blockIdx.y * 128, bn = blockIdx.x * 256;

    float acc[4][8][4];
#pragma unroll
    for (int mi = 0; mi < 4; ++mi)
#pragma unroll
        for (int ni = 0; ni < 8; ++ni)
#pragma unroll
            for (int j = 0; j < 4; ++j) acc[mi][ni][j] = 0.f;

    const int nk = K >> 5;
    gemm_load_stage(sb, A, B, bm, bn, K, 0, tid);
    CP_COMMIT();
    gemm_load_stage(sb + GSTAGE, A, B, bm, bn, K, 32, tid);
    CP_COMMIT();

    for (int ks = 0; ks < nk; ++ks) {
        CP_WAIT1();
        __syncthreads();
        const uint32_t sA = sb + (uint32_t)(ks & 1) * GSTAGE;
        const uint32_t sB = sA + GA_BYTES;

#pragma unroll
        for (int kk = 0; kk < 2; ++kk) {
            const uint32_t colo = (uint32_t)(kk * 32 + (lane >> 4) * 16);
            uint32_t af[4][4], bf[8][2];
#pragma unroll
            for (int mi = 0; mi < 4; ++mi) {
                uint32_t ro = (uint32_t)(wr * 64 + mi * 16 + (lane & 15)) * 80 + colo;
                ldsm_x4(af[mi], sA + ro);
            }
#pragma unroll
            for (int nj = 0; nj < 4; ++nj) {
                uint32_t ro = (uint32_t)(wc * 64 + nj * 16 + (lane & 15)) * 80 + colo;
                uint32_t t[4];
                ldsm_x4(t, sB + ro);
                bf[nj * 2][0] = t[0]; bf[nj * 2][1] = t[2];
                bf[nj * 2 + 1][0] = t[1]; bf[nj * 2 + 1][1] = t[3];
            }
#pragma unroll
            for (int mi = 0; mi < 4; ++mi)
#pragma unroll
                for (int ni = 0; ni < 8; ++ni)
                    mma_f16(acc[mi][ni], af[mi], bf[ni]);
        }

        __syncthreads();
        if (ks + 2 < nk)
            gemm_load_stage(sb + (uint32_t)(ks & 1) * GSTAGE, A, B,
                            bm, bn, K, (ks + 2) * 32, tid);
        CP_COMMIT();
    }

    // epilogue
#pragma unroll
    for (int mi = 0; mi < 4; ++mi) {
        int row = bm + wr * 64 + mi * 16 + (lane >> 2);
#pragma unroll
        for (int ni = 0; ni < 8; ++ni) {
            int col = bn + wc * 64 + ni * 8 + (lane & 3) * 2;
            if (HALF_OUT) {
                __half* C = (__half*)Cv;
                __half2 h0 = __floats2half2_rn(acc[mi][ni][0], acc[mi][ni][1]);
                __half2 h1 = __floats2half2_rn(acc[mi][ni][2], acc[mi][ni][3]);
                *(__half2*)&C[(size_t)row * N + col] = h0;
                *(__half2*)&C[(size_t)(row + 8) * N + col] = h1;
            } else {
                float* C = (float*)Cv;
                float2 v0 = make_float2(acc[mi][ni][0], acc[mi][ni][1]);
                float2 v1 = make_float2(acc[mi][ni][2], acc[mi][ni][3]);
                *(float2*)&C[(size_t)row * N + col] = v0;
                *(float2*)&C[(size_t)(row + 8) * N + col] = v1;
            }
        }
    }
}

// ---------------------------------------------------------------------------
// Prep: RoPE (q,k) + head-major relayout (B,H,T,D). Reads fp16 qkv.
// Q gets hi/lo split (compensated S pass); K,V plain fp16.
// ---------------------------------------------------------------------------
__global__ void rope_split_kernel(const __half* __restrict__ qkv,
                                  __half* __restrict__ Qhi, __half* __restrict__ Qlo,
                                  __half* __restrict__ Kh, __half* __restrict__ Vh)
{
    int idx = blockIdx.x * blockDim.x + threadIdx.x;
    int i = idx & 31;
    int h = (idx >> 5) & 15;
    int t = (idx >> 9) & 2047;
    int b = idx >> 20;

    float p = powf(10000.0f, (float)(2 * i) * (1.0f / 64.0f));
    float ang = (float)t * (1.0f / p);
    float sn, cs;
    sincosf(ang, &sn, &cs);

    size_t src = ((size_t)(b * T_SEQ + t)) * QKV_COLS + h * D_HEAD;
    size_t dst = ((size_t)((b * H_DIM + h) * T_SEQ + t)) * D_HEAD;

    // q (fold 1/8 scale), hi/lo
    {
        float q1 = __half2float(qkv[src + i]);
        float q2 = __half2float(qkv[src + i + 32]);
        float a = (q1 * cs + q2 * sn) * 0.125f;
        float c2 = (-q1 * sn + q2 * cs) * 0.125f;
        __half ha = __float2half_rn(a), hc = __float2half_rn(c2);
        Qhi[dst + i] = ha; Qhi[dst + i + 32] = hc;
        Qlo[dst + i] = __float2half_rn(a - __half2float(ha));
        Qlo[dst + i + 32] = __float2half_rn(c2 - __half2float(hc));
    }
    // k (plain fp16)
    {
        float k1 = __half2float(qkv[src + C_DIM + i]);
        float k2 = __half2float(qkv[src + C_DIM + i + 32]);
        Kh[dst + i]      = __float2half_rn(k1 * cs + k2 * sn);
        Kh[dst + i + 32] = __float2half_rn(-k1 * sn + k2 * cs);
    }
    // v (pass-through fp16)
    {
        Vh[dst + i]      = qkv[src + 2 * C_DIM + i];
        Vh[dst + i + 32] = qkv[src + 2 * C_DIM + i + 32];
    }
}

// ---------------------------------------------------------------------------
// Flash attention via mma.sync fp16, causal.
// CTA: 128 queries x one (b,h); 8 warps x 16 rows. 64-key tiles, double buffer.
// S: 2-pass (Qhi,Qlo) x K.  PV: single-pass fp16 P.
// ---------------------------------------------------------------------------
#define FPITCH 144u
#define FTILE  (64u * FPITCH)          // 9216
#define FSTAGE (2u * FTILE)            // Kh, Vh = 18432
#define FL_SMEM (2u * FSTAGE)          // 36864 (also covers Q staging)

__device__ __forceinline__ void flash_load_stage(
    uint32_t dstbase, int kb,
    const __half* __restrict__ Kh, const __half* __restrict__ Vh, int tid)
{
#pragma unroll
    for (int j = 0; j < 4; ++j) {
        int idx = tid + j * 256;
        int tile = idx >> 9;                   // 0..1
        int r = (idx >> 3) & 63;
        int c = idx & 7;
        uint32_t dst = dstbase + (uint32_t)tile * FTILE + (uint32_t)r * FPITCH + c * 16;
        const __half* src = (tile == 0 ? Kh : Vh);
        CP_ASYNC16(dst, src + (size_t)(kb + r) * D_HEAD + c * 8);
    }
}

__global__ void __launch_bounds__(256) flash_mma_kernel(
    const __half* __restrict__ Qhi, const __half* __restrict__ Qlo,
    const __half* __restrict__ Khg, const __half* __restrict__ Vhg,
    __half* __restrict__ yh)
{
    extern __shared__ char fsm[];
    const uint32_t sb = smem_to_u32(fsm);
    const int tid = threadIdx.x;
    const int lane = tid & 31, w = tid >> 5;
    const int qt = gridDim.x - 1 - blockIdx.x;     // heavy tiles first
    const int bh = blockIdx.y;
    const int qb = qt * 128;

    const size_t hoff = (size_t)bh * T_SEQ * D_HEAD;
    const __half* Qh = Qhi + hoff + (size_t)qb * D_HEAD;
    const __half* Ql = Qlo + hoff + (size_t)qb * D_HEAD;
    const __half* Kh = Khg + hoff;
    const __half* Vh = Vhg + hoff;

    // ---- stage Q (hi at sb, lo at sb+128*FPITCH), extract A fragments ----
#pragma unroll
    for (int j = 0; j < 8; ++j) {
        int idx = tid + j * 256;               // 2048 chunks
        int tile = idx >> 10;
        int r = (idx >> 3) & 127;
        int c = idx & 7;
        uint32_t dst = sb + (uint32_t)tile * (128u * FPITCH) + (uint32_t)r * FPITCH + c * 16;
        const __half* src = (tile == 0 ? Qh : Ql);
        CP_ASYNC16(dst, src + (size_t)r * D_HEAD + c * 8);
    }
    CP_COMMIT();
    CP_WAIT0();
    __syncthreads();

    uint32_t qhf[4][4], qlf[4][4];
    {
        uint32_t arow = (uint32_t)(w * 16 + (lane & 7) + ((lane & 8) ? 8 : 0));
        uint32_t acol = (uint32_t)(((lane & 16) ? 16 : 0));
#pragma unroll
        for (int kk = 0; kk < 4; ++kk) {
            uint32_t a = sb + arow * FPITCH + kk * 32 + acol;
            ldsm_x4(qhf[kk], a);
            ldsm_x4(qlf[kk], a + 128u * FPITCH);
        }
    }
    __syncthreads();   // Q fragments extracted; smem reusable

    float o[8][4];
#pragma unroll
    for (int j = 0; j < 8; ++j)
#pragma unroll
        for (int c = 0; c < 4; ++c) o[j][c] = 0.f;
    float m0 = -1e30f, m1 = -1e30f, l0 = 0.f, l1 = 0.f;

    const int ntiles = 2 * qt + 2;
    const int wqmin = qb + w * 16;
    const int wqmax = wqmin + 15;

    flash_load_stage(sb, 0, Kh, Vh, tid);
    CP_COMMIT();
    flash_load_stage(sb + FSTAGE, 64, Kh, Vh, tid);
    CP_COMMIT();

    for (int kt = 0; kt < ntiles; ++kt) {
        CP_WAIT1();
        __syncthreads();
        const uint32_t stage = sb + (uint32_t)(kt & 1) * FSTAGE;
        const int kb = kt * 64;

        if (kb <= wqmax) {
            // ---- S = Q K^T (2-pass Q hi/lo) ----
            float s[8][4];
#pragma unroll
            for (int j = 0; j < 8; ++j)
#pragma unroll
                for (int c = 0; c < 4; ++c) s[j][c] = 0.f;

            const uint32_t br = (uint32_t)((lane & 7) + ((lane & 16) ? 8 : 0));
            const uint32_t bc = (uint32_t)((lane & 8) ? 16 : 0);
#pragma unroll
            for (int kg = 0; kg < 4; ++kg) {
                uint32_t rowa = (uint32_t)(kg * 16) + br;
#pragma unroll
                for (int kk = 0; kk < 4; ++kk) {
                    uint32_t addr = stage + rowa * FPITCH + kk * 32 + bc;
                    uint32_t k4[4];
                    ldsm_x4(k4, addr);
                    mma_f16(s[2 * kg],     qhf[kk], &k4[0]);
                    mma_f16(s[2 * kg + 1], qhf[kk], &k4[2]);
                    mma_f16(s[2 * kg],     qlf[kk], &k4[0]);
                    mma_f16(s[2 * kg + 1], qlf[kk], &k4[2]);
                }
            }

            // ---- causal mask ----
            if (kb + 63 > wqmin) {
                int r0 = wqmin + (lane >> 2), r1 = r0 + 8;
#pragma unroll
                for (int j = 0; j < 8; ++j) {
                    int k0 = kb + j * 8 + ((lane & 3) << 1);
                    if (k0 > r0)     s[j][0] = -1e30f;
                    if (k0 + 1 > r0) s[j][1] = -1e30f;
                    if (k0 > r1)     s[j][2] = -1e30f;
                    if (k0 + 1 > r1) s[j][3] = -1e30f;
                }
            }

            // ---- online softmax ----
            float mx0 = -1e30f, mx1 = -1e30f;
#pragma unroll
            for (int j = 0; j < 8; ++j) {
                mx0 = fmaxf(mx0, fmaxf(s[j][0], s[j][1]));
                mx1 = fmaxf(mx1, fmaxf(s[j][2], s[j][3]));
            }
            mx0 = fmaxf(mx0, __shfl_xor_sync(0xffffffffu, mx0, 1));
            mx0 = fmaxf(mx0, __shfl_xor_sync(0xffffffffu, mx0, 2));
            mx1 = fmaxf(mx1, __shfl_xor_sync(0xffffffffu, mx1, 1));
            mx1 = fmaxf(mx1, __shfl_xor_sync(0xffffffffu, mx1, 2));
            float m0n = fmaxf(m0, mx0), m1n = fmaxf(m1, mx1);
            float sc0 = __expf(m0 - m0n), sc1 = __expf(m1 - m1n);
            float rs0 = 0.f, rs1 = 0.f;
#pragma unroll
            for (int j = 0; j < 8; ++j) {
                s[j][0] = __expf(s[j][0] - m0n);
                s[j][1] = __expf(s[j][1] - m0n);
                s[j][2] = __expf(s[j][2] - m1n);
                s[j][3] = __expf(s[j][3] - m1n);
                rs0 += s[j][0] + s[j][1];
                rs1 += s[j][2] + s[j][3];
            }
            rs0 += __shfl_xor_sync(0xffffffffu, rs0, 1);
            rs0 += __shfl_xor_sync(0xffffffffu, rs0, 2);
            rs1 += __shfl_xor_sync(0xffffffffu, rs1, 1);
            rs1 += __shfl_xor_sync(0xffffffffu, rs1, 2);
            l0 = l0 * sc0 + rs0;
            l1 = l1 * sc1 + rs1;
            m0 = m0n; m1 = m1n;
#pragma unroll
            for (int j = 0; j < 8; ++j) {
                o[j][0] *= sc0; o[j][1] *= sc0;
                o[j][2] *= sc1; o[j][3] *= sc1;
            }

            // ---- pack P fp16 A-fragments (single precision pass) ----
            uint32_t aph[4][4];
#pragma unroll
            for (int kk2 = 0; kk2 < 4; ++kk2) {
                int j0 = 2 * kk2, j1 = j0 + 1;
                __half2 p0 = __floats2half2_rn(s[j0][0], s[j0][1]);
                __half2 p1 = __floats2half2_rn(s[j0][2], s[j0][3]);
                __half2 p2 = __floats2half2_rn(s[j1][0], s[j1][1]);
                __half2 p3 = __floats2half2_rn(s[j1][2], s[j1][3]);
                aph[kk2][0] = *(uint32_t*)&p0;
                aph[kk2][1] = *(uint32_t*)&p1;
                aph[kk2][2] = *(uint32_t*)&p2;
                aph[kk2][3] = *(uint32_t*)&p3;
            }

            // ---- O += P V (single pass) via ldmatrix.trans on V ----
            const uint32_t vr = (uint32_t)((lane & 7) + ((lane & 8) ? 8 : 0));
            const uint32_t vc = (uint32_t)((lane & 16) ? 16 : 0);
#pragma unroll
            for (int dg = 0; dg < 4; ++dg) {
#pragma unroll
                for (int kk2 = 0; kk2 < 4; ++kk2) {
                    uint32_t addr = stage + FTILE +
                                    (uint32_t)(kk2 * 16 + vr) * FPITCH + dg * 32 + vc;
                    uint32_t v4[4];
                    ldsm_x4t(v4, addr);
                    mma_f16(o[2 * dg],     aph[kk2], &v4[0]);
                    mma_f16(o[2 * dg + 1], aph[kk2], &v4[2]);
                }
            }
        }

        __syncthreads();
        if (kt + 2 < ntiles)
            flash_load_stage(sb + (uint32_t)(kt & 1) * FSTAGE, (kt + 2) * 64,
                             Kh, Vh, tid);
        CP_COMMIT();
    }

    // ---- normalize and write fp16 (proj GEMM A-operand) ----
    const float inv0 = 1.0f / l0, inv1 = 1.0f / l1;
    const int b = bh >> 4, h = bh & 15;
    const int r0 = qb + w * 16 + (lane >> 2);
#pragma unroll
    for (int j = 0; j < 8; ++j) {
        int col = h * 64 + j * 8 + (lane & 3) * 2;
        __half2 hh0 = __floats2half2_rn(o[j][0] * inv0, o[j][1] * inv0);
        __half2 hh1 = __floats2half2_rn(o[j][2] * inv1, o[j][3] * inv1);
        *(__half2*)&yh[(size_t)(b * T_SEQ + r0) * C_DIM + col] = hh0;
        *(__half2*)&yh[(size_t)(b * T_SEQ + r0 + 8) * C_DIM + col] = hh1;
    }
}

// ---------------------------------------------------------------------------
extern "C" void kernel_launch(void* const* d_in, const int* in_sizes, int n_in,
                              void* d_out, int out_size)
{
    const float* x      = (const float*)d_in[0];
    const float* w_attn = (const float*)d_in[1];
    const float* w_proj = (const float*)d_in[2];
    float* out = (float*)d_out;

    __half *qkv16, *x16, *wa, *wp, *yh;
    __half *Qhi, *Qlo, *Kh, *Vh;
    cudaGetSymbolAddress((void**)&qkv16, g_qkv16);
    cudaGetSymbolAddress((void**)&x16, g_x16);
    cudaGetSymbolAddress((void**)&wa, g_wa);
    cudaGetSymbolAddress((void**)&wp, g_wp);
    cudaGetSymbolAddress((void**)&yh, g_yh);
    cudaGetSymbolAddress((void**)&Qhi, g_Qhi);
    cudaGetSymbolAddress((void**)&Qlo, g_Qlo);
    cudaGetSymbolAddress((void**)&Kh, g_Kh);
    cudaGetSymbolAddress((void**)&Vh, g_Vh);

    static bool attr_set = false;
    if (!attr_set) {
        cudaFuncSetAttribute(gemm_f16_kernel<true>,
                             cudaFuncAttributeMaxDynamicSharedMemorySize, GEMM_SMEM);
        cudaFuncSetAttribute(gemm_f16_kernel<false>,
                             cudaFuncAttributeMaxDynamicSharedMemorySize, GEMM_SMEM);
        cudaFuncSetAttribute(flash_mma_kernel,
                             cudaFuncAttributeMaxDynamicSharedMemorySize, FL_SMEM);
        attr_set = true;
    }

    // input conversions
    {
        int n4 = M_ROWS * C_DIM / 4;
        conv_f16_kernel<<<(n4 + 255) / 256, 256>>>(x, x16, n4);
        n4 = QKV_COLS * C_DIM / 4;
        conv_f16_kernel<<<(n4 + 255) / 256, 256>>>(w_attn, wa, n4);
        n4 = C_DIM * C_DIM / 4;
        conv_f16_kernel<<<(n4 + 255) / 256, 256>>>(w_proj, wp, n4);
    }
    // 1) qkv = x @ w_attn^T   (fp16 HMMA, fp16 output)
    {
        dim3 grid(QKV_COLS / 256, M_ROWS / 128);
        gemm_f16_kernel<true><<<grid, 256, GEMM_SMEM>>>(x16, wa, qkv16,
                                                        QKV_COLS, C_DIM);
    }
    // 2) RoPE + relayout (fp16 in/out)
    {
        int total = B_DIM * T_SEQ * H_DIM * 32;
        rope_split_kernel<<<total / 256, 256>>>(qkv16, Qhi, Qlo, Kh, Vh);
    }
    // 3) flash attention (tensor cores) -> yh fp16
    {
        dim3 grid(T_SEQ / 128, B_DIM * H_DIM);
        flash_mma_kernel<<<grid, 256, FL_SMEM>>>(Qhi, Qlo, Kh, Vh, yh);
    }
    // 4) out = y @ w_proj^T   (fp16 HMMA, fp32 output)
    {
        dim3 grid(C_DIM / 256, M_ROWS / 128);
        gemm_f16_kernel<false><<<grid, 256, GEMM_SMEM>>>(yh, wp, out,
                                                         C_DIM, C_DIM);
    }
}

// round 9
// speedup vs baseline: 2.0729x; 1.0462x over previous
#include <cuda_runtime.h>
#include <cuda_bf16.h>
#include <cuda_fp16.h>
#include <cstdint>
#include <math.h>

#define B_DIM 2
#define T_SEQ 2048
#define C_DIM 1024
#define H_DIM 16
#define D_HEAD 64
#define M_ROWS (B_DIM * T_SEQ)       // 4096
#define QKV_COLS (3 * C_DIM)         // 3072

// ---------------------------------------------------------------------------
// Scratch (allocation-free rule: __device__ globals)
// ---------------------------------------------------------------------------
__device__ __half g_qkv16[(size_t)M_ROWS * QKV_COLS]; // qkv fp16 (B,T,3,H,D)

__device__ __half g_x16[(size_t)M_ROWS * C_DIM];     // x fp16
__device__ __half g_wa [(size_t)QKV_COLS * C_DIM];   // w_attn fp16
__device__ __half g_wp [(size_t)C_DIM * C_DIM];      // w_proj fp16
__device__ __half g_yh [(size_t)M_ROWS * C_DIM];     // attention out fp16

// head-major fp16 Q(hi/lo), K, V: (B,H,T,D)
#define HD_ELEMS ((size_t)B_DIM * H_DIM * T_SEQ * D_HEAD)
__device__ __half g_Qhi[HD_ELEMS];
__device__ __half g_Qlo[HD_ELEMS];
__device__ __half g_Kh [HD_ELEMS];
__device__ __half g_Vh [HD_ELEMS];

// ---------------------------------------------------------------------------
// helpers
// ---------------------------------------------------------------------------
__device__ __forceinline__ uint32_t smem_to_u32(const void* smem_ptr) {
    uint32_t addr;
    asm("{ .reg .u64 tmp; cvta.to.shared.u64 tmp, %1; cvt.u32.u64 %0, tmp; }"
        : "=r"(addr) : "l"(smem_ptr));
    return addr;
}

#define CP_ASYNC16(dst_u32, src_ptr) \
    asm volatile("cp.async.cg.shared.global [%0], [%1], 16;" \
        :: "r"(dst_u32), "l"(__cvta_generic_to_global(src_ptr)))
#define CP_COMMIT() asm volatile("cp.async.commit_group;")
#define CP_WAIT1()  asm volatile("cp.async.wait_group 1;")
#define CP_WAIT0()  asm volatile("cp.async.wait_group 0;")

__device__ __forceinline__ void ldsm_x4(uint32_t* r, uint32_t addr) {
    asm volatile("ldmatrix.sync.aligned.m8n8.x4.shared.b16 {%0,%1,%2,%3}, [%4];"
        : "=r"(r[0]), "=r"(r[1]), "=r"(r[2]), "=r"(r[3]) : "r"(addr));
}
__device__ __forceinline__ void ldsm_x4t(uint32_t* r, uint32_t addr) {
    asm volatile("ldmatrix.sync.aligned.m8n8.x4.trans.shared.b16 {%0,%1,%2,%3}, [%4];"
        : "=r"(r[0]), "=r"(r[1]), "=r"(r[2]), "=r"(r[3]) : "r"(addr));
}
__device__ __forceinline__ void mma_f16(float* d, const uint32_t* a, const uint32_t* b) {
    asm volatile(
        "mma.sync.aligned.m16n8k16.row.col.f32.f16.f16.f32 "
        "{%0,%1,%2,%3}, {%4,%5,%6,%7}, {%8,%9}, {%0,%1,%2,%3};"
        : "+f"(d[0]), "+f"(d[1]), "+f"(d[2]), "+f"(d[3])
        : "r"(a[0]), "r"(a[1]), "r"(a[2]), "r"(a[3]), "r"(b[0]), "r"(b[1]));
}

// ---------------------------------------------------------------------------
// fp32 -> fp16 convert
// ---------------------------------------------------------------------------
__global__ void conv_f16_kernel(const float* __restrict__ x,
                                __half* __restrict__ hi, int n4)
{
    int i = blockIdx.x * blockDim.x + threadIdx.x;
    if (i >= n4) return;
    float4 v = ((const float4*)x)[i];
    __half2 hp0 = __floats2half2_rn(v.x, v.y);
    __half2 hp1 = __floats2half2_rn(v.z, v.w);
    ((__half2*)hi)[2 * i]     = hp0;
    ((__half2*)hi)[2 * i + 1] = hp1;
}

// ---------------------------------------------------------------------------
// Tensor-core GEMM NT via mma.sync fp16, single pass:
//   C[M,N] = A[M,K] * B[N,K]^T
// 128x128 CTA tile, BK=32, 256 threads (8 warps 2x4, 64x32 warp tiles),
// cp.async 3-stage pipeline (one __syncthreads per K-step), 80B smem pitch.
// ---------------------------------------------------------------------------
#define GTILE 10240u                  // 128 rows * 80B
#define GSTAGE (2 * GTILE)            // A, B = 20480
#define GEMM_SMEM (3 * GSTAGE)        // 61440

__device__ __forceinline__ void gemm_load_stage(
    uint32_t sdst,
    const __half* __restrict__ A, const __half* __restrict__ B,
    int bm, int bn, int K, int k0, int tid)
{
#pragma unroll
    for (int i = 0; i < 2; ++i) {
        int idx = tid + i * 256;           // 0..511 -> (row, 16B-chunk)
        int r = idx >> 2, c = idx & 3;
        uint32_t so = (uint32_t)(r * 80 + c * 16);
        size_t ga = (size_t)(bm + r) * K + k0 + c * 8;
        size_t gb = (size_t)(bn + r) * K + k0 + c * 8;
        CP_ASYNC16(sdst + so,         A + ga);
        CP_ASYNC16(sdst + GTILE + so, B + gb);
    }
}

template<bool HALF_OUT>
__global__ void __launch_bounds__(256) gemm_f16_kernel(
    const __half* __restrict__ A, const __half* __restrict__ B,
    void* __restrict__ Cv, int N, int K)
{
    extern __shared__ char smem[];
    const uint32_t sb = smem_to_u32(smem);
    const int tid = threadIdx.x;
    const int lane = tid & 31, wid = tid >> 5;
    const int wr = wid >> 2, wc = wid & 3;          // warp grid 2x4
    const int bm = blockIdx.y * 128, bn = blockIdx.x * 128;

    float acc[4][4][4];
#pragma unroll
    for (int mi = 0; mi < 4; ++mi)
#pragma unroll
        for (int ni = 0; ni < 4; ++ni)
#pragma unroll
            for (int j = 0; j < 4; ++j) acc[mi][ni][j] = 0.f;

    const int nk = K >> 5;
    // prologue: stages 0, 1
    gemm_load_stage(sb, A, B, bm, bn, K, 0, tid);
    CP_COMMIT();
    gemm_load_stage(sb + GSTAGE, A, B, bm, bn, K, 32, tid);
    CP_COMMIT();

    uint32_t bufs[3] = {sb, sb + GSTAGE, sb + 2 * GSTAGE};
    int cur = 0, nxt = 2;

    for (int ks = 0; ks < nk; ++ks) {
        CP_WAIT1();               // stage ks ready (<=1 group pending)
        __syncthreads();          // all warps done reading buf nxt (= ks-1 mod 3)

        // issue loads for stage ks+2 into buf (ks+2)%3 = nxt
        if (ks + 2 < nk)
            gemm_load_stage(bufs[nxt], A, B, bm, bn, K, (ks + 2) * 32, tid);
        CP_COMMIT();

        const uint32_t sA = bufs[cur];
        const uint32_t sB = sA + GTILE;

#pragma unroll
        for (int kk = 0; kk < 2; ++kk) {
            const uint32_t colo = (uint32_t)(kk * 32 + (lane >> 4) * 16);
            uint32_t af[4][4], bf[4][2];
#pragma unroll
            for (int mi = 0; mi < 4; ++mi) {
                uint32_t ro = (uint32_t)(wr * 64 + mi * 16 + (lane & 15)) * 80 + colo;
                ldsm_x4(af[mi], sA + ro);
            }
#pragma unroll
            for (int nj = 0; nj < 2; ++nj) {
                uint32_t ro = (uint32_t)(wc * 32 + nj * 16 + (lane & 15)) * 80 + colo;
                uint32_t t[4];
                ldsm_x4(t, sB + ro);
                bf[nj * 2][0] = t[0]; bf[nj * 2][1] = t[2];
                bf[nj * 2 + 1][0] = t[1]; bf[nj * 2 + 1][1] = t[3];
            }
#pragma unroll
            for (int mi = 0; mi < 4; ++mi)
#pragma unroll
                for (int ni = 0; ni < 4; ++ni)
                    mma_f16(acc[mi][ni], af[mi], bf[ni]);
        }

        cur = (cur + 1) % 3;
        nxt = (nxt + 1) % 3;
    }

    // epilogue
#pragma unroll
    for (int mi = 0; mi < 4; ++mi) {
        int row = bm + wr * 64 + mi * 16 + (lane >> 2);
#pragma unroll
        for (int ni = 0; ni < 4; ++ni) {
            int col = bn + wc * 32 + ni * 8 + (lane & 3) * 2;
            if (HALF_OUT) {
                __half* C = (__half*)Cv;
                __half2 h0 = __floats2half2_rn(acc[mi][ni][0], acc[mi][ni][1]);
                __half2 h1 = __floats2half2_rn(acc[mi][ni][2], acc[mi][ni][3]);
                *(__half2*)&C[(size_t)row * N + col] = h0;
                *(__half2*)&C[(size_t)(row + 8) * N + col] = h1;
            } else {
                float* C = (float*)Cv;
                float2 v0 = make_float2(acc[mi][ni][0], acc[mi][ni][1]);
                float2 v1 = make_float2(acc[mi][ni][2], acc[mi][ni][3]);
                *(float2*)&C[(size_t)row * N + col] = v0;
                *(float2*)&C[(size_t)(row + 8) * N + col] = v1;
            }
        }
    }
}

// ---------------------------------------------------------------------------
// Prep: RoPE (q,k) + head-major relayout (B,H,T,D). Reads fp16 qkv.
// Q gets hi/lo split (compensated S pass); K,V plain fp16.
// ---------------------------------------------------------------------------
__global__ void rope_split_kernel(const __half* __restrict__ qkv,
                                  __half* __restrict__ Qhi, __half* __restrict__ Qlo,
                                  __half* __restrict__ Kh, __half* __restrict__ Vh)
{
    int idx = blockIdx.x * blockDim.x + threadIdx.x;
    int i = idx & 31;
    int h = (idx >> 5) & 15;
    int t = (idx >> 9) & 2047;
    int b = idx >> 20;

    float p = powf(10000.0f, (float)(2 * i) * (1.0f / 64.0f));
    float ang = (float)t * (1.0f / p);
    float sn, cs;
    sincosf(ang, &sn, &cs);

    size_t src = ((size_t)(b * T_SEQ + t)) * QKV_COLS + h * D_HEAD;
    size_t dst = ((size_t)((b * H_DIM + h) * T_SEQ + t)) * D_HEAD;

    // q (fold 1/8 scale), hi/lo
    {
        float q1 = __half2float(qkv[src + i]);
        float q2 = __half2float(qkv[src + i + 32]);
        float a = (q1 * cs + q2 * sn) * 0.125f;
        float c2 = (-q1 * sn + q2 * cs) * 0.125f;
        __half ha = __float2half_rn(a), hc = __float2half_rn(c2);
        Qhi[dst + i] = ha; Qhi[dst + i + 32] = hc;
        Qlo[dst + i] = __float2half_rn(a - __half2float(ha));
        Qlo[dst + i + 32] = __float2half_rn(c2 - __half2float(hc));
    }
    // k (plain fp16)
    {
        float k1 = __half2float(qkv[src + C_DIM + i]);
        float k2 = __half2float(qkv[src + C_DIM + i + 32]);
        Kh[dst + i]      = __float2half_rn(k1 * cs + k2 * sn);
        Kh[dst + i + 32] = __float2half_rn(-k1 * sn + k2 * cs);
    }
    // v (pass-through fp16)
    {
        Vh[dst + i]      = qkv[src + 2 * C_DIM + i];
        Vh[dst + i + 32] = qkv[src + 2 * C_DIM + i + 32];
    }
}

// ---------------------------------------------------------------------------
// Flash attention via mma.sync fp16, causal.
// CTA: 128 queries x one (b,h); 8 warps x 16 rows. 64-key tiles,
// 3-stage cp.async pipeline (one __syncthreads per tile).
// S: 2-pass (Qhi,Qlo) x K.  PV: single-pass fp16 P.
// ---------------------------------------------------------------------------
#define FPITCH 144u
#define FTILE  (64u * FPITCH)          // 9216
#define FSTAGE (2u * FTILE)            // Kh, Vh = 18432
#define FL_SMEM (3u * FSTAGE)          // 55296 (also covers Q staging 36864)

__device__ __forceinline__ void flash_load_stage(
    uint32_t dstbase, int kb,
    const __half* __restrict__ Kh, const __half* __restrict__ Vh, int tid)
{
#pragma unroll
    for (int j = 0; j < 4; ++j) {
        int idx = tid + j * 256;
        int tile = idx >> 9;                   // 0..1
        int r = (idx >> 3) & 63;
        int c = idx & 7;
        uint32_t dst = dstbase + (uint32_t)tile * FTILE + (uint32_t)r * FPITCH + c * 16;
        const __half* src = (tile == 0 ? Kh : Vh);
        CP_ASYNC16(dst, src + (size_t)(kb + r) * D_HEAD + c * 8);
    }
}

__global__ void __launch_bounds__(256) flash_mma_kernel(
    const __half* __restrict__ Qhi, const __half* __restrict__ Qlo,
    const __half* __restrict__ Khg, const __half* __restrict__ Vhg,
    __half* __restrict__ yh)
{
    extern __shared__ char fsm[];
    const uint32_t sb = smem_to_u32(fsm);
    const int tid = threadIdx.x;
    const int lane = tid & 31, w = tid >> 5;
    const int qt = gridDim.x - 1 - blockIdx.x;     // heavy tiles first
    const int bh = blockIdx.y;
    const int qb = qt * 128;

    const size_t hoff = (size_t)bh * T_SEQ * D_HEAD;
    const __half* Qh = Qhi + hoff + (size_t)qb * D_HEAD;
    const __half* Ql = Qlo + hoff + (size_t)qb * D_HEAD;
    const __half* Kh = Khg + hoff;
    const __half* Vh = Vhg + hoff;

    // ---- stage Q (hi at sb, lo at sb+128*FPITCH), extract A fragments ----
#pragma unroll
    for (int j = 0; j < 8; ++j) {
        int idx = tid + j * 256;               // 2048 chunks
        int tile = idx >> 10;
        int r = (idx >> 3) & 127;
        int c = idx & 7;
        uint32_t dst = sb + (uint32_t)tile * (128u * FPITCH) + (uint32_t)r * FPITCH + c * 16;
        const __half* src = (tile == 0 ? Qh : Ql);
        CP_ASYNC16(dst, src + (size_t)r * D_HEAD + c * 8);
    }
    CP_COMMIT();
    CP_WAIT0();
    __syncthreads();

    uint32_t qhf[4][4], qlf[4][4];
    {
        uint32_t arow = (uint32_t)(w * 16 + (lane & 7) + ((lane & 8) ? 8 : 0));
        uint32_t acol = (uint32_t)(((lane & 16) ? 16 : 0));
#pragma unroll
        for (int kk = 0; kk < 4; ++kk) {
            uint32_t a = sb + arow * FPITCH + kk * 32 + acol;
            ldsm_x4(qhf[kk], a);
            ldsm_x4(qlf[kk], a + 128u * FPITCH);
        }
    }
    __syncthreads();   // Q fragments extracted; smem reusable

    float o[8][4];
#pragma unroll
    for (int j = 0; j < 8; ++j)
#pragma unroll
        for (int c = 0; c < 4; ++c) o[j][c] = 0.f;
    float m0 = -1e30f, m1 = -1e30f, l0 = 0.f, l1 = 0.f;

    const int ntiles = 2 * qt + 2;
    const int wqmin = qb + w * 16;
    const int wqmax = wqmin + 15;

    flash_load_stage(sb, 0, Kh, Vh, tid);
    CP_COMMIT();
    flash_load_stage(sb + FSTAGE, 64, Kh, Vh, tid);
    CP_COMMIT();

    uint32_t bufs[3] = {sb, sb + FSTAGE, sb + 2 * FSTAGE};
    int cur = 0, nxt = 2;

    for (int kt = 0; kt < ntiles; ++kt) {
        CP_WAIT1();
        __syncthreads();

        if (kt + 2 < ntiles)
            flash_load_stage(bufs[nxt], (kt + 2) * 64, Kh, Vh, tid);
        CP_COMMIT();

        const uint32_t stage = bufs[cur];
        const int kb = kt * 64;

        if (kb <= wqmax) {
            // ---- S = Q K^T (2-pass Q hi/lo) ----
            float s[8][4];
#pragma unroll
            for (int j = 0; j < 8; ++j)
#pragma unroll
                for (int c = 0; c < 4; ++c) s[j][c] = 0.f;

            const uint32_t br = (uint32_t)((lane & 7) + ((lane & 16) ? 8 : 0));
            const uint32_t bc = (uint32_t)((lane & 8) ? 16 : 0);
#pragma unroll
            for (int kg = 0; kg < 4; ++kg) {
                uint32_t rowa = (uint32_t)(kg * 16) + br;
#pragma unroll
                for (int kk = 0; kk < 4; ++kk) {
                    uint32_t addr = stage + rowa * FPITCH + kk * 32 + bc;
                    uint32_t k4[4];
                    ldsm_x4(k4, addr);
                    mma_f16(s[2 * kg],     qhf[kk], &k4[0]);
                    mma_f16(s[2 * kg + 1], qhf[kk], &k4[2]);
                    mma_f16(s[2 * kg],     qlf[kk], &k4[0]);
                    mma_f16(s[2 * kg + 1], qlf[kk], &k4[2]);
                }
            }

            // ---- causal mask ----
            if (kb + 63 > wqmin) {
                int r0 = wqmin + (lane >> 2), r1 = r0 + 8;
#pragma unroll
                for (int j = 0; j < 8; ++j) {
                    int k0 = kb + j * 8 + ((lane & 3) << 1);
                    if (k0 > r0)     s[j][0] = -1e30f;
                    if (k0 + 1 > r0) s[j][1] = -1e30f;
                    if (k0 > r1)     s[j][2] = -1e30f;
                    if (k0 + 1 > r1) s[j][3] = -1e30f;
                }
            }

            // ---- online softmax ----
            float mx0 = -1e30f, mx1 = -1e30f;
#pragma unroll
            for (int j = 0; j < 8; ++j) {
                mx0 = fmaxf(mx0, fmaxf(s[j][0], s[j][1]));
                mx1 = fmaxf(mx1, fmaxf(s[j][2], s[j][3]));
            }
            mx0 = fmaxf(mx0, __shfl_xor_sync(0xffffffffu, mx0, 1));
            mx0 = fmaxf(mx0, __shfl_xor_sync(0xffffffffu, mx0, 2));
            mx1 = fmaxf(mx1, __shfl_xor_sync(0xffffffffu, mx1, 1));
            mx1 = fmaxf(mx1, __shfl_xor_sync(0xffffffffu, mx1, 2));
            float m0n = fmaxf(m0, mx0), m1n = fmaxf(m1, mx1);
            float sc0 = __expf(m0 - m0n), sc1 = __expf(m1 - m1n);
            float rs0 = 0.f, rs1 = 0.f;
#pragma unroll
            for (int j = 0; j < 8; ++j) {
                s[j][0] = __expf(s[j][0] - m0n);
                s[j][1] = __expf(s[j][1] - m0n);
                s[j][2] = __expf(s[j][2] - m1n);
                s[j][3] = __expf(s[j][3] - m1n);
                rs0 += s[j][0] + s[j][1];
                rs1 += s[j][2] + s[j][3];
            }
            rs0 += __shfl_xor_sync(0xffffffffu, rs0, 1);
            rs0 += __shfl_xor_sync(0xffffffffu, rs0, 2);
            rs1 += __shfl_xor_sync(0xffffffffu, rs1, 1);
            rs1 += __shfl_xor_sync(0xffffffffu, rs1, 2);
            l0 = l0 * sc0 + rs0;
            l1 = l1 * sc1 + rs1;
            m0 = m0n; m1 = m1n;
#pragma unroll
            for (int j = 0; j < 8; ++j) {
                o[j][0] *= sc0; o[j][1] *= sc0;
                o[j][2] *= sc1; o[j][3] *= sc1;
            }

            // ---- pack P fp16 A-fragments (single precision pass) ----
            uint32_t aph[4][4];
#pragma unroll
            for (int kk2 = 0; kk2 < 4; ++kk2) {
                int j0 = 2 * kk2, j1 = j0 + 1;
                __half2 p0 = __floats2half2_rn(s[j0][0], s[j0][1]);
                __half2 p1 = __floats2half2_rn(s[j0][2], s[j0][3]);
                __half2 p2 = __floats2half2_rn(s[j1][0], s[j1][1]);
                __half2 p3 = __floats2half2_rn(s[j1][2], s[j1][3]);
                aph[kk2][0] = *(uint32_t*)&p0;
                aph[kk2][1] = *(uint32_t*)&p1;
                aph[kk2][2] = *(uint32_t*)&p2;
                aph[kk2][3] = *(uint32_t*)&p3;
            }

            // ---- O += P V (single pass) via ldmatrix.trans on V ----
            const uint32_t vr = (uint32_t)((lane & 7) + ((lane & 8) ? 8 : 0));
            const uint32_t vc = (uint32_t)((lane & 16) ? 16 : 0);
#pragma unroll
            for (int dg = 0; dg < 4; ++dg) {
#pragma unroll
                for (int kk2 = 0; kk2 < 4; ++kk2) {
                    uint32_t addr = stage + FTILE +
                                    (uint32_t)(kk2 * 16 + vr) * FPITCH + dg * 32 + vc;
                    uint32_t v4[4];
                    ldsm_x4t(v4, addr);
                    mma_f16(o[2 * dg],     aph[kk2], &v4[0]);
                    mma_f16(o[2 * dg + 1], aph[kk2], &v4[2]);
                }
            }
        }

        cur = (cur + 1) % 3;
        nxt = (nxt + 1) % 3;
    }

    // ---- normalize and write fp16 (proj GEMM A-operand) ----
    const float inv0 = 1.0f / l0, inv1 = 1.0f / l1;
    const int b = bh >> 4, h = bh & 15;
    const int r0 = qb + w * 16 + (lane >> 2);
#pragma unroll
    for (int j = 0; j < 8; ++j) {
        int col = h * 64 + j * 8 + (lane & 3) * 2;
        __half2 hh0 = __floats2half2_rn(o[j][0] * inv0, o[j][1] * inv0);
        __half2 hh1 = __floats2half2_rn(o[j][2] * inv1, o[j][3] * inv1);
        *(__half2*)&yh[(size_t)(b * T_SEQ + r0) * C_DIM + col] = hh0;
        *(__half2*)&yh[(size_t)(b * T_SEQ + r0 + 8) * C_DIM + col] = hh1;
    }
}

// ---------------------------------------------------------------------------
extern "C" void kernel_launch(void* const* d_in, const int* in_sizes, int n_in,
                              void* d_out, int out_size)
{
    const float* x      = (const float*)d_in[0];
    const float* w_attn = (const float*)d_in[1];
    const float* w_proj = (const float*)d_in[2];
    float* out = (float*)d_out;

    __half *qkv16, *x16, *wa, *wp, *yh;
    __half *Qhi, *Qlo, *Kh, *Vh;
    cudaGetSymbolAddress((void**)&qkv16, g_qkv16);
    cudaGetSymbolAddress((void**)&x16, g_x16);
    cudaGetSymbolAddress((void**)&wa, g_wa);
    cudaGetSymbolAddress((void**)&wp, g_wp);
    cudaGetSymbolAddress((void**)&yh, g_yh);
    cudaGetSymbolAddress((void**)&Qhi, g_Qhi);
    cudaGetSymbolAddress((void**)&Qlo, g_Qlo);
    cudaGetSymbolAddress((void**)&Kh, g_Kh);
    cudaGetSymbolAddress((void**)&Vh, g_Vh);

    static bool attr_set = false;
    if (!attr_set) {
        cudaFuncSetAttribute(gemm_f16_kernel<true>,
                             cudaFuncAttributeMaxDynamicSharedMemorySize, GEMM_SMEM);
        cudaFuncSetAttribute(gemm_f16_kernel<false>,
                             cudaFuncAttributeMaxDynamicSharedMemorySize, GEMM_SMEM);
        cudaFuncSetAttribute(flash_mma_kernel,
                             cudaFuncAttributeMaxDynamicSharedMemorySize, FL_SMEM);
        attr_set = true;
    }

    // input conversions
    {
        int n4 = M_ROWS * C_DIM / 4;
        conv_f16_kernel<<<(n4 + 255) / 256, 256>>>(x, x16, n4);
        n4 = QKV_COLS * C_DIM / 4;
        conv_f16_kernel<<<(n4 + 255) / 256, 256>>>(w_attn, wa, n4);
        n4 = C_DIM * C_DIM / 4;
        conv_f16_kernel<<<(n4 + 255) / 256, 256>>>(w_proj, wp, n4);
    }
    // 1) qkv = x @ w_attn^T   (fp16 HMMA, fp16 output)
    {
        dim3 grid(QKV_COLS / 128, M_ROWS / 128);
        gemm_f16_kernel<true><<<grid, 256, GEMM_SMEM>>>(x16, wa, qkv16,
                                                        QKV_COLS, C_DIM);
    }
    // 2) RoPE + relayout (fp16 in/out)
    {
        int total = B_DIM * T_SEQ * H_DIM * 32;
        rope_split_kernel<<<total / 256, 256>>>(qkv16, Qhi, Qlo, Kh, Vh);
    }
    // 3) flash attention (tensor cores) -> yh fp16
    {
        dim3 grid(T_SEQ / 128, B_DIM * H_DIM);
        flash_mma_kernel<<<grid, 256, FL_SMEM>>>(Qhi, Qlo, Kh, Vh, yh);
    }
    // 4) out = y @ w_proj^T   (fp16 HMMA, fp32 output)
    {
        dim3 grid(C_DIM / 128, M_ROWS / 128);
        gemm_f16_kernel<false><<<grid, 256, GEMM_SMEM>>>(yh, wp, out,
                                                         C_DIM, C_DIM);
    }
}

// round 10
// speedup vs baseline: 2.2600x; 1.0903x over previous
#include <cuda_runtime.h>
#include <cuda_bf16.h>
#include <cuda_fp16.h>
#include <cstdint>
#include <math.h>

#define B_DIM 2
#define T_SEQ 2048
#define C_DIM 1024
#define H_DIM 16
#define D_HEAD 64
#define M_ROWS (B_DIM * T_SEQ)       // 4096
#define QKV_COLS (3 * C_DIM)         // 3072

// ---------------------------------------------------------------------------
// Scratch (allocation-free rule: __device__ globals)
// ---------------------------------------------------------------------------
__device__ __half g_qkv16[(size_t)M_ROWS * QKV_COLS]; // qkv fp16 (B,T,3,H,D)

__device__ __half g_x16[(size_t)M_ROWS * C_DIM];     // x fp16
__device__ __half g_wa [(size_t)QKV_COLS * C_DIM];   // w_attn fp16
__device__ __half g_wp [(size_t)C_DIM * C_DIM];      // w_proj fp16
__device__ __half g_yh [(size_t)M_ROWS * C_DIM];     // attention out fp16

// head-major fp16 Q, K, V: (B,H,T,D)
#define HD_ELEMS ((size_t)B_DIM * H_DIM * T_SEQ * D_HEAD)
__device__ __half g_Qh [HD_ELEMS];
__device__ __half g_Kh [HD_ELEMS];
__device__ __half g_Vh [HD_ELEMS];

// ---------------------------------------------------------------------------
// helpers
// ---------------------------------------------------------------------------
__device__ __forceinline__ uint32_t smem_to_u32(const void* smem_ptr) {
    uint32_t addr;
    asm("{ .reg .u64 tmp; cvta.to.shared.u64 tmp, %1; cvt.u32.u64 %0, tmp; }"
        : "=r"(addr) : "l"(smem_ptr));
    return addr;
}

#define CP_ASYNC16(dst_u32, src_ptr) \
    asm volatile("cp.async.cg.shared.global [%0], [%1], 16;" \
        :: "r"(dst_u32), "l"(__cvta_generic_to_global(src_ptr)))
#define CP_COMMIT() asm volatile("cp.async.commit_group;")
#define CP_WAIT1()  asm volatile("cp.async.wait_group 1;")
#define CP_WAIT0()  asm volatile("cp.async.wait_group 0;")

__device__ __forceinline__ void ldsm_x4(uint32_t* r, uint32_t addr) {
    asm volatile("ldmatrix.sync.aligned.m8n8.x4.shared.b16 {%0,%1,%2,%3}, [%4];"
        : "=r"(r[0]), "=r"(r[1]), "=r"(r[2]), "=r"(r[3]) : "r"(addr));
}
__device__ __forceinline__ void ldsm_x4t(uint32_t* r, uint32_t addr) {
    asm volatile("ldmatrix.sync.aligned.m8n8.x4.trans.shared.b16 {%0,%1,%2,%3}, [%4];"
        : "=r"(r[0]), "=r"(r[1]), "=r"(r[2]), "=r"(r[3]) : "r"(addr));
}
__device__ __forceinline__ void mma_f16(float* d, const uint32_t* a, const uint32_t* b) {
    asm volatile(
        "mma.sync.aligned.m16n8k16.row.col.f32.f16.f16.f32 "
        "{%0,%1,%2,%3}, {%4,%5,%6,%7}, {%8,%9}, {%0,%1,%2,%3};"
        : "+f"(d[0]), "+f"(d[1]), "+f"(d[2]), "+f"(d[3])
        : "r"(a[0]), "r"(a[1]), "r"(a[2]), "r"(a[3]), "r"(b[0]), "r"(b[1]));
}

// ---------------------------------------------------------------------------
// fused fp32 -> fp16 convert for x, w_attn, w_proj (single launch)
// ---------------------------------------------------------------------------
#define N4_X  (M_ROWS * C_DIM / 4)       // 1048576
#define N4_WA (QKV_COLS * C_DIM / 4)     // 786432
#define N4_WP (C_DIM * C_DIM / 4)        // 262144
#define N4_ALL (N4_X + N4_WA + N4_WP)    // 2097152

__global__ void conv_all_kernel(const float* __restrict__ x,
                                const float* __restrict__ waf,
                                const float* __restrict__ wpf,
                                __half* __restrict__ x16,
                                __half* __restrict__ wa,
                                __half* __restrict__ wp)
{
    int i = blockIdx.x * blockDim.x + threadIdx.x;
    const float* src;
    __half* dst;
    int j;
    if (i < N4_X)               { src = x;   dst = x16; j = i; }
    else if (i < N4_X + N4_WA)  { src = waf; dst = wa;  j = i - N4_X; }
    else if (i < N4_ALL)        { src = wpf; dst = wp;  j = i - N4_X - N4_WA; }
    else return;
    float4 v = ((const float4*)src)[j];
    __half2 hp0 = __floats2half2_rn(v.x, v.y);
    __half2 hp1 = __floats2half2_rn(v.z, v.w);
    ((__half2*)dst)[2 * j]     = hp0;
    ((__half2*)dst)[2 * j + 1] = hp1;
}

// ---------------------------------------------------------------------------
// Tensor-core GEMM NT via mma.sync fp16, single pass:
//   C[M,N] = A[M,K] * B[N,K]^T
// 128x128 CTA tile, BK=32, 256 threads (8 warps 2x4, 64x32 warp tiles),
// cp.async 3-stage pipeline (one __syncthreads per K-step), 80B smem pitch.
// ---------------------------------------------------------------------------
#define GTILE 10240u                  // 128 rows * 80B
#define GSTAGE (2 * GTILE)            // A, B = 20480
#define GEMM_SMEM (3 * GSTAGE)        // 61440

__device__ __forceinline__ void gemm_load_stage(
    uint32_t sdst,
    const __half* __restrict__ A, const __half* __restrict__ B,
    int bm, int bn, int K, int k0, int tid)
{
#pragma unroll
    for (int i = 0; i < 2; ++i) {
        int idx = tid + i * 256;           // 0..511 -> (row, 16B-chunk)
        int r = idx >> 2, c = idx & 3;
        uint32_t so = (uint32_t)(r * 80 + c * 16);
        size_t ga = (size_t)(bm + r) * K + k0 + c * 8;
        size_t gb = (size_t)(bn + r) * K + k0 + c * 8;
        CP_ASYNC16(sdst + so,         A + ga);
        CP_ASYNC16(sdst + GTILE + so, B + gb);
    }
}

template<bool HALF_OUT>
__global__ void __launch_bounds__(256) gemm_f16_kernel(
    const __half* __restrict__ A, const __half* __restrict__ B,
    void* __restrict__ Cv, int N, int K)
{
    extern __shared__ char smem[];
    const uint32_t sb = smem_to_u32(smem);
    const int tid = threadIdx.x;
    const int lane = tid & 31, wid = tid >> 5;
    const int wr = wid >> 2, wc = wid & 3;          // warp grid 2x4
    const int bm = blockIdx.y * 128, bn = blockIdx.x * 128;

    float acc[4][4][4];
#pragma unroll
    for (int mi = 0; mi < 4; ++mi)
#pragma unroll
        for (int ni = 0; ni < 4; ++ni)
#pragma unroll
            for (int j = 0; j < 4; ++j) acc[mi][ni][j] = 0.f;

    const int nk = K >> 5;
    gemm_load_stage(sb, A, B, bm, bn, K, 0, tid);
    CP_COMMIT();
    gemm_load_stage(sb + GSTAGE, A, B, bm, bn, K, 32, tid);
    CP_COMMIT();

    uint32_t bufs[3] = {sb, sb + GSTAGE, sb + 2 * GSTAGE};
    int cur = 0, nxt = 2;

    for (int ks = 0; ks < nk; ++ks) {
        CP_WAIT1();
        __syncthreads();

        if (ks + 2 < nk)
            gemm_load_stage(bufs[nxt], A, B, bm, bn, K, (ks + 2) * 32, tid);
        CP_COMMIT();

        const uint32_t sA = bufs[cur];
        const uint32_t sB = sA + GTILE;

#pragma unroll
        for (int kk = 0; kk < 2; ++kk) {
            const uint32_t colo = (uint32_t)(kk * 32 + (lane >> 4) * 16);
            uint32_t af[4][4], bf[4][2];
#pragma unroll
            for (int mi = 0; mi < 4; ++mi) {
                uint32_t ro = (uint32_t)(wr * 64 + mi * 16 + (lane & 15)) * 80 + colo;
                ldsm_x4(af[mi], sA + ro);
            }
#pragma unroll
            for (int nj = 0; nj < 2; ++nj) {
                uint32_t ro = (uint32_t)(wc * 32 + nj * 16 + (lane & 15)) * 80 + colo;
                uint32_t t[4];
                ldsm_x4(t, sB + ro);
                bf[nj * 2][0] = t[0]; bf[nj * 2][1] = t[2];
                bf[nj * 2 + 1][0] = t[1]; bf[nj * 2 + 1][1] = t[3];
            }
#pragma unroll
            for (int mi = 0; mi < 4; ++mi)
#pragma unroll
                for (int ni = 0; ni < 4; ++ni)
                    mma_f16(acc[mi][ni], af[mi], bf[ni]);
        }

        cur = (cur + 1) % 3;
        nxt = (nxt + 1) % 3;
    }

    // epilogue
#pragma unroll
    for (int mi = 0; mi < 4; ++mi) {
        int row = bm + wr * 64 + mi * 16 + (lane >> 2);
#pragma unroll
        for (int ni = 0; ni < 4; ++ni) {
            int col = bn + wc * 32 + ni * 8 + (lane & 3) * 2;
            if (HALF_OUT) {
                __half* C = (__half*)Cv;
                __half2 h0 = __floats2half2_rn(acc[mi][ni][0], acc[mi][ni][1]);
                __half2 h1 = __floats2half2_rn(acc[mi][ni][2], acc[mi][ni][3]);
                *(__half2*)&C[(size_t)row * N + col] = h0;
                *(__half2*)&C[(size_t)(row + 8) * N + col] = h1;
            } else {
                float* C = (float*)Cv;
                float2 v0 = make_float2(acc[mi][ni][0], acc[mi][ni][1]);
                float2 v1 = make_float2(acc[mi][ni][2], acc[mi][ni][3]);
                *(float2*)&C[(size_t)row * N + col] = v0;
                *(float2*)&C[(size_t)(row + 8) * N + col] = v1;
            }
        }
    }
}

// ---------------------------------------------------------------------------
// Prep: RoPE (q,k) + head-major relayout (B,H,T,D). Reads fp16 qkv.
// ---------------------------------------------------------------------------
__global__ void rope_split_kernel(const __half* __restrict__ qkv,
                                  __half* __restrict__ Qh,
                                  __half* __restrict__ Kh, __half* __restrict__ Vh)
{
    int idx = blockIdx.x * blockDim.x + threadIdx.x;
    int i = idx & 31;
    int h = (idx >> 5) & 15;
    int t = (idx >> 9) & 2047;
    int b = idx >> 20;

    float p = powf(10000.0f, (float)(2 * i) * (1.0f / 64.0f));
    float ang = (float)t * (1.0f / p);
    float sn, cs;
    sincosf(ang, &sn, &cs);

    size_t src = ((size_t)(b * T_SEQ + t)) * QKV_COLS + h * D_HEAD;
    size_t dst = ((size_t)((b * H_DIM + h) * T_SEQ + t)) * D_HEAD;

    // q (fold 1/8 scale)
    {
        float q1 = __half2float(qkv[src + i]);
        float q2 = __half2float(qkv[src + i + 32]);
        Qh[dst + i]      = __float2half_rn((q1 * cs + q2 * sn) * 0.125f);
        Qh[dst + i + 32] = __float2half_rn((-q1 * sn + q2 * cs) * 0.125f);
    }
    // k
    {
        float k1 = __half2float(qkv[src + C_DIM + i]);
        float k2 = __half2float(qkv[src + C_DIM + i + 32]);
        Kh[dst + i]      = __float2half_rn(k1 * cs + k2 * sn);
        Kh[dst + i + 32] = __float2half_rn(-k1 * sn + k2 * cs);
    }
    // v (pass-through)
    {
        Vh[dst + i]      = qkv[src + 2 * C_DIM + i];
        Vh[dst + i + 32] = qkv[src + 2 * C_DIM + i + 32];
    }
}

// ---------------------------------------------------------------------------
// Flash attention via mma.sync fp16, causal.
// CTA: 128 queries x one (b,h); 8 warps x 16 rows. 64-key tiles,
// 3-stage cp.async pipeline (one __syncthreads per tile).
// S: single pass.  PV: single pass.
// ---------------------------------------------------------------------------
#define FPITCH 144u
#define FTILE  (64u * FPITCH)          // 9216
#define FSTAGE (2u * FTILE)            // Kh, Vh = 18432
#define FL_SMEM (3u * FSTAGE)          // 55296 (covers Q staging 18432)

__device__ __forceinline__ void flash_load_stage(
    uint32_t dstbase, int kb,
    const __half* __restrict__ Kh, const __half* __restrict__ Vh, int tid)
{
#pragma unroll
    for (int j = 0; j < 4; ++j) {
        int idx = tid + j * 256;
        int tile = idx >> 9;                   // 0..1
        int r = (idx >> 3) & 63;
        int c = idx & 7;
        uint32_t dst = dstbase + (uint32_t)tile * FTILE + (uint32_t)r * FPITCH + c * 16;
        const __half* src = (tile == 0 ? Kh : Vh);
        CP_ASYNC16(dst, src + (size_t)(kb + r) * D_HEAD + c * 8);
    }
}

__global__ void __launch_bounds__(256) flash_mma_kernel(
    const __half* __restrict__ Qhg,
    const __half* __restrict__ Khg, const __half* __restrict__ Vhg,
    __half* __restrict__ yh)
{
    extern __shared__ char fsm[];
    const uint32_t sb = smem_to_u32(fsm);
    const int tid = threadIdx.x;
    const int lane = tid & 31, w = tid >> 5;
    const int qt = gridDim.x - 1 - blockIdx.x;     // heavy tiles first
    const int bh = blockIdx.y;
    const int qb = qt * 128;

    const size_t hoff = (size_t)bh * T_SEQ * D_HEAD;
    const __half* Qh = Qhg + hoff + (size_t)qb * D_HEAD;
    const __half* Kh = Khg + hoff;
    const __half* Vh = Vhg + hoff;

    // ---- stage Q and extract A fragments ----
#pragma unroll
    for (int j = 0; j < 4; ++j) {
        int idx = tid + j * 256;               // 1024 chunks: 128 rows x 8
        int r = idx >> 3;
        int c = idx & 7;
        uint32_t dst = sb + (uint32_t)r * FPITCH + c * 16;
        CP_ASYNC16(dst, Qh + (size_t)r * D_HEAD + c * 8);
    }
    CP_COMMIT();
    CP_WAIT0();
    __syncthreads();

    uint32_t qhf[4][4];
    {
        uint32_t arow = (uint32_t)(w * 16 + (lane & 7) + ((lane & 8) ? 8 : 0));
        uint32_t acol = (uint32_t)(((lane & 16) ? 16 : 0));
#pragma unroll
        for (int kk = 0; kk < 4; ++kk)
            ldsm_x4(qhf[kk], sb + arow * FPITCH + kk * 32 + acol);
    }
    __syncthreads();   // Q fragments extracted; smem reusable

    float o[8][4];
#pragma unroll
    for (int j = 0; j < 8; ++j)
#pragma unroll
        for (int c = 0; c < 4; ++c) o[j][c] = 0.f;
    float m0 = -1e30f, m1 = -1e30f, l0 = 0.f, l1 = 0.f;

    const int ntiles = 2 * qt + 2;
    const int wqmin = qb + w * 16;
    const int wqmax = wqmin + 15;

    flash_load_stage(sb, 0, Kh, Vh, tid);
    CP_COMMIT();
    flash_load_stage(sb + FSTAGE, 64, Kh, Vh, tid);
    CP_COMMIT();

    uint32_t bufs[3] = {sb, sb + FSTAGE, sb + 2 * FSTAGE};
    int cur = 0, nxt = 2;

    for (int kt = 0; kt < ntiles; ++kt) {
        CP_WAIT1();
        __syncthreads();

        if (kt + 2 < ntiles)
            flash_load_stage(bufs[nxt], (kt + 2) * 64, Kh, Vh, tid);
        CP_COMMIT();

        const uint32_t stage = bufs[cur];
        const int kb = kt * 64;

        if (kb <= wqmax) {
            // ---- S = Q K^T (single pass) ----
            float s[8][4];
#pragma unroll
            for (int j = 0; j < 8; ++j)
#pragma unroll
                for (int c = 0; c < 4; ++c) s[j][c] = 0.f;

            const uint32_t br = (uint32_t)((lane & 7) + ((lane & 16) ? 8 : 0));
            const uint32_t bc = (uint32_t)((lane & 8) ? 16 : 0);
#pragma unroll
            for (int kg = 0; kg < 4; ++kg) {
                uint32_t rowa = (uint32_t)(kg * 16) + br;
#pragma unroll
                for (int kk = 0; kk < 4; ++kk) {
                    uint32_t addr = stage + rowa * FPITCH + kk * 32 + bc;
                    uint32_t k4[4];
                    ldsm_x4(k4, addr);
                    mma_f16(s[2 * kg],     qhf[kk], &k4[0]);
                    mma_f16(s[2 * kg + 1], qhf[kk], &k4[2]);
                }
            }

            // ---- causal mask ----
            if (kb + 63 > wqmin) {
                int r0 = wqmin + (lane >> 2), r1 = r0 + 8;
#pragma unroll
                for (int j = 0; j < 8; ++j) {
                    int k0 = kb + j * 8 + ((lane & 3) << 1);
                    if (k0 > r0)     s[j][0] = -1e30f;
                    if (k0 + 1 > r0) s[j][1] = -1e30f;
                    if (k0 > r1)     s[j][2] = -1e30f;
                    if (k0 + 1 > r1) s[j][3] = -1e30f;
                }
            }

            // ---- online softmax ----
            float mx0 = -1e30f, mx1 = -1e30f;
#pragma unroll
            for (int j = 0; j < 8; ++j) {
                mx0 = fmaxf(mx0, fmaxf(s[j][0], s[j][1]));
                mx1 = fmaxf(mx1, fmaxf(s[j][2], s[j][3]));
            }
            mx0 = fmaxf(mx0, __shfl_xor_sync(0xffffffffu, mx0, 1));
            mx0 = fmaxf(mx0, __shfl_xor_sync(0xffffffffu, mx0, 2));
            mx1 = fmaxf(mx1, __shfl_xor_sync(0xffffffffu, mx1, 1));
            mx1 = fmaxf(mx1, __shfl_xor_sync(0xffffffffu, mx1, 2));
            float m0n = fmaxf(m0, mx0), m1n = fmaxf(m1, mx1);
            float sc0 = __expf(m0 - m0n), sc1 = __expf(m1 - m1n);
            float rs0 = 0.f, rs1 = 0.f;
#pragma unroll
            for (int j = 0; j < 8; ++j) {
                s[j][0] = __expf(s[j][0] - m0n);
                s[j][1] = __expf(s[j][1] - m0n);
                s[j][2] = __expf(s[j][2] - m1n);
                s[j][3] = __expf(s[j][3] - m1n);
                rs0 += s[j][0] + s[j][1];
                rs1 += s[j][2] + s[j][3];
            }
            rs0 += __shfl_xor_sync(0xffffffffu, rs0, 1);
            rs0 += __shfl_xor_sync(0xffffffffu, rs0, 2);
            rs1 += __shfl_xor_sync(0xffffffffu, rs1, 1);
            rs1 += __shfl_xor_sync(0xffffffffu, rs1, 2);
            l0 = l0 * sc0 + rs0;
            l1 = l1 * sc1 + rs1;
            m0 = m0n; m1 = m1n;
#pragma unroll
            for (int j = 0; j < 8; ++j) {
                o[j][0] *= sc0; o[j][1] *= sc0;
                o[j][2] *= sc1; o[j][3] *= sc1;
            }

            // ---- pack P fp16 A-fragments ----
            uint32_t aph[4][4];
#pragma unroll
            for (int kk2 = 0; kk2 < 4; ++kk2) {
                int j0 = 2 * kk2, j1 = j0 + 1;
                __half2 p0 = __floats2half2_rn(s[j0][0], s[j0][1]);
                __half2 p1 = __floats2half2_rn(s[j0][2], s[j0][3]);
                __half2 p2 = __floats2half2_rn(s[j1][0], s[j1][1]);
                __half2 p3 = __floats2half2_rn(s[j1][2], s[j1][3]);
                aph[kk2][0] = *(uint32_t*)&p0;
                aph[kk2][1] = *(uint32_t*)&p1;
                aph[kk2][2] = *(uint32_t*)&p2;
                aph[kk2][3] = *(uint32_t*)&p3;
            }

            // ---- O += P V (single pass) via ldmatrix.trans on V ----
            const uint32_t vr = (uint32_t)((lane & 7) + ((lane & 8) ? 8 : 0));
            const uint32_t vc = (uint32_t)((lane & 16) ? 16 : 0);
#pragma unroll
            for (int dg = 0; dg < 4; ++dg) {
#pragma unroll
                for (int kk2 = 0; kk2 < 4; ++kk2) {
                    uint32_t addr = stage + FTILE +
                                    (uint32_t)(kk2 * 16 + vr) * FPITCH + dg * 32 + vc;
                    uint32_t v4[4];
                    ldsm_x4t(v4, addr);
                    mma_f16(o[2 * dg],     aph[kk2], &v4[0]);
                    mma_f16(o[2 * dg + 1], aph[kk2], &v4[2]);
                }
            }
        }

        cur = (cur + 1) % 3;
        nxt = (nxt + 1) % 3;
    }

    // ---- normalize and write fp16 (proj GEMM A-operand) ----
    const float inv0 = 1.0f / l0, inv1 = 1.0f / l1;
    const int b = bh >> 4, h = bh & 15;
    const int r0 = qb + w * 16 + (lane >> 2);
#pragma unroll
    for (int j = 0; j < 8; ++j) {
        int col = h * 64 + j * 8 + (lane & 3) * 2;
        __half2 hh0 = __floats2half2_rn(o[j][0] * inv0, o[j][1] * inv0);
        __half2 hh1 = __floats2half2_rn(o[j][2] * inv1, o[j][3] * inv1);
        *(__half2*)&yh[(size_t)(b * T_SEQ + r0) * C_DIM + col] = hh0;
        *(__half2*)&yh[(size_t)(b * T_SEQ + r0 + 8) * C_DIM + col] = hh1;
    }
}

// ---------------------------------------------------------------------------
extern "C" void kernel_launch(void* const* d_in, const int* in_sizes, int n_in,
                              void* d_out, int out_size)
{
    const float* x      = (const float*)d_in[0];
    const float* w_attn = (const float*)d_in[1];
    const float* w_proj = (const float*)d_in[2];
    float* out = (float*)d_out;

    __half *qkv16, *x16, *wa, *wp, *yh;
    __half *Qh, *Kh, *Vh;
    cudaGetSymbolAddress((void**)&qkv16, g_qkv16);
    cudaGetSymbolAddress((void**)&x16, g_x16);
    cudaGetSymbolAddress((void**)&wa, g_wa);
    cudaGetSymbolAddress((void**)&wp, g_wp);
    cudaGetSymbolAddress((void**)&yh, g_yh);
    cudaGetSymbolAddress((void**)&Qh, g_Qh);
    cudaGetSymbolAddress((void**)&Kh, g_Kh);
    cudaGetSymbolAddress((void**)&Vh, g_Vh);

    static bool attr_set = false;
    if (!attr_set) {
        cudaFuncSetAttribute(gemm_f16_kernel<true>,
                             cudaFuncAttributeMaxDynamicSharedMemorySize, GEMM_SMEM);
        cudaFuncSetAttribute(gemm_f16_kernel<false>,
                             cudaFuncAttributeMaxDynamicSharedMemorySize, GEMM_SMEM);
        cudaFuncSetAttribute(flash_mma_kernel,
                             cudaFuncAttributeMaxDynamicSharedMemorySize, FL_SMEM);
        attr_set = true;
    }

    // fused input conversions (1 launch)
    conv_all_kernel<<<N4_ALL / 256, 256>>>(x, w_attn, w_proj, x16, wa, wp);

    // 1) qkv = x @ w_attn^T   (fp16 HMMA, fp16 output)
    {
        dim3 grid(QKV_COLS / 128, M_ROWS / 128);
        gemm_f16_kernel<true><<<grid, 256, GEMM_SMEM>>>(x16, wa, qkv16,
                                                        QKV_COLS, C_DIM);
    }
    // 2) RoPE + relayout (fp16 in/out)
    {
        int total = B_DIM * T_SEQ * H_DIM * 32;
        rope_split_kernel<<<total / 256, 256>>>(qkv16, Qh, Kh, Vh);
    }
    // 3) flash attention (tensor cores) -> yh fp16
    {
        dim3 grid(T_SEQ / 128, B_DIM * H_DIM);
        flash_mma_kernel<<<grid, 256, FL_SMEM>>>(Qh, Kh, Vh, yh);
    }
    // 4) out = y @ w_proj^T   (fp16 HMMA, fp32 output)
    {
        dim3 grid(C_DIM / 128, M_ROWS / 128);
        gemm_f16_kernel<false><<<grid, 256, GEMM_SMEM>>>(yh, wp, out,
                                                         C_DIM, C_DIM);
    }
}

// round 12
// speedup vs baseline: 2.3058x; 1.0203x over previous
#include <cuda_runtime.h>
#include <cuda_bf16.h>
#include <cuda_fp16.h>
#include <cstdint>
#include <math.h>

#define B_DIM 2
#define T_SEQ 2048
#define C_DIM 1024
#define H_DIM 16
#define D_HEAD 64
#define M_ROWS (B_DIM * T_SEQ)       // 4096
#define QKV_COLS (3 * C_DIM)         // 3072

// ---------------------------------------------------------------------------
// Scratch (allocation-free rule: __device__ globals)
// ---------------------------------------------------------------------------
__device__ __half g_qkv16[(size_t)M_ROWS * QKV_COLS]; // qkv fp16 (B,T,3,H,D)

__device__ __half g_x16[(size_t)M_ROWS * C_DIM];     // x fp16
__device__ __half g_wa [(size_t)QKV_COLS * C_DIM];   // w_attn fp16
__device__ __half g_wp [(size_t)C_DIM * C_DIM];      // w_proj fp16
__device__ __half g_yh [(size_t)M_ROWS * C_DIM];     // attention out fp16

// head-major fp16 Q, K, V: (B,H,T,D)
#define HD_ELEMS ((size_t)B_DIM * H_DIM * T_SEQ * D_HEAD)
__device__ __half g_Qh [HD_ELEMS];
__device__ __half g_Kh [HD_ELEMS];
__device__ __half g_Vh [HD_ELEMS];

// ---------------------------------------------------------------------------
// helpers
// ---------------------------------------------------------------------------
__device__ __forceinline__ uint32_t smem_to_u32(const void* smem_ptr) {
    uint32_t addr;
    asm("{ .reg .u64 tmp; cvta.to.shared.u64 tmp, %1; cvt.u32.u64 %0, tmp; }"
        : "=r"(addr) : "l"(smem_ptr));
    return addr;
}

#define CP_ASYNC16(dst_u32, src_ptr) \
    asm volatile("cp.async.cg.shared.global [%0], [%1], 16;" \
        :: "r"(dst_u32), "l"(__cvta_generic_to_global(src_ptr)))
#define CP_COMMIT() asm volatile("cp.async.commit_group;")
#define CP_WAIT1()  asm volatile("cp.async.wait_group 1;")
#define CP_WAIT0()  asm volatile("cp.async.wait_group 0;")

__device__ __forceinline__ void ldsm_x4(uint32_t* r, uint32_t addr) {
    asm volatile("ldmatrix.sync.aligned.m8n8.x4.shared.b16 {%0,%1,%2,%3}, [%4];"
        : "=r"(r[0]), "=r"(r[1]), "=r"(r[2]), "=r"(r[3]) : "r"(addr));
}
__device__ __forceinline__ void ldsm_x4t(uint32_t* r, uint32_t addr) {
    asm volatile("ldmatrix.sync.aligned.m8n8.x4.trans.shared.b16 {%0,%1,%2,%3}, [%4];"
        : "=r"(r[0]), "=r"(r[1]), "=r"(r[2]), "=r"(r[3]) : "r"(addr));
}
__device__ __forceinline__ void mma_f16(float* d, const uint32_t* a, const uint32_t* b) {
    asm volatile(
        "mma.sync.aligned.m16n8k16.row.col.f32.f16.f16.f32 "
        "{%0,%1,%2,%3}, {%4,%5,%6,%7}, {%8,%9}, {%0,%1,%2,%3};"
        : "+f"(d[0]), "+f"(d[1]), "+f"(d[2]), "+f"(d[3])
        : "r"(a[0]), "r"(a[1]), "r"(a[2]), "r"(a[3]), "r"(b[0]), "r"(b[1]));
}
__device__ __forceinline__ float ex2f(float x) {
    float r;
    asm("ex2.approx.f32 %0, %1;" : "=f"(r) : "f"(x));
    return r;
}

// ---------------------------------------------------------------------------
// fused fp32 -> fp16 convert for x, w_attn, w_proj (single launch)
// ---------------------------------------------------------------------------
#define N4_X  (M_ROWS * C_DIM / 4)       // 1048576
#define N4_WA (QKV_COLS * C_DIM / 4)     // 786432
#define N4_WP (C_DIM * C_DIM / 4)        // 262144
#define N4_ALL (N4_X + N4_WA + N4_WP)    // 2097152

__global__ void conv_all_kernel(const float* __restrict__ x,
                                const float* __restrict__ waf,
                                const float* __restrict__ wpf,
                                __half* __restrict__ x16,
                                __half* __restrict__ wa,
                                __half* __restrict__ wp)
{
    int i = blockIdx.x * blockDim.x + threadIdx.x;
    const float* src;
    __half* dst;
    int j;
    if (i < N4_X)               { src = x;   dst = x16; j = i; }
    else if (i < N4_X + N4_WA)  { src = waf; dst = wa;  j = i - N4_X; }
    else if (i < N4_ALL)        { src = wpf; dst = wp;  j = i - N4_X - N4_WA; }
    else return;
    float4 v = ((const float4*)src)[j];
    __half2 hp0 = __floats2half2_rn(v.x, v.y);
    __half2 hp1 = __floats2half2_rn(v.z, v.w);
    ((__half2*)dst)[2 * j]     = hp0;
    ((__half2*)dst)[2 * j + 1] = hp1;
}

// ---------------------------------------------------------------------------
// Tensor-core GEMM NT via mma.sync fp16, single pass:
//   C[M,N] = A[M,K] * B[N,K]^T
// 128x128 CTA tile, BK=32, 256 threads (8 warps 2x4, 64x32 warp tiles),
// cp.async 3-stage pipeline, 80B smem pitch.
// ---------------------------------------------------------------------------
#define GTILE 10240u                  // 128 rows * 80B
#define GSTAGE (2 * GTILE)            // A, B = 20480
#define GEMM_SMEM (3 * GSTAGE)        // 61440

__device__ __forceinline__ void gemm_load_stage(
    uint32_t sdst,
    const __half* __restrict__ A, const __half* __restrict__ B,
    int bm, int bn, int K, int k0, int tid)
{
#pragma unroll
    for (int i = 0; i < 2; ++i) {
        int idx = tid + i * 256;           // 0..511 -> (row, 16B-chunk)
        int r = idx >> 2, c = idx & 3;
        uint32_t so = (uint32_t)(r * 80 + c * 16);
        size_t ga = (size_t)(bm + r) * K + k0 + c * 8;
        size_t gb = (size_t)(bn + r) * K + k0 + c * 8;
        CP_ASYNC16(sdst + so,         A + ga);
        CP_ASYNC16(sdst + GTILE + so, B + gb);
    }
}

template<bool HALF_OUT>
__global__ void __launch_bounds__(256) gemm_f16_kernel(
    const __half* __restrict__ A, const __half* __restrict__ B,
    void* __restrict__ Cv, int N, int K)
{
    extern __shared__ char smem[];
    const uint32_t sb = smem_to_u32(smem);
    const int tid = threadIdx.x;
    const int lane = tid & 31, wid = tid >> 5;
    const int wr = wid >> 2, wc = wid & 3;          // warp grid 2x4
    const int bm = blockIdx.y * 128, bn = blockIdx.x * 128;

    float acc[4][4][4];
#pragma unroll
    for (int mi = 0; mi < 4; ++mi)
#pragma unroll
        for (int ni = 0; ni < 4; ++ni)
#pragma unroll
            for (int j = 0; j < 4; ++j) acc[mi][ni][j] = 0.f;

    const int nk = K >> 5;
    gemm_load_stage(sb, A, B, bm, bn, K, 0, tid);
    CP_COMMIT();
    gemm_load_stage(sb + GSTAGE, A, B, bm, bn, K, 32, tid);
    CP_COMMIT();

    uint32_t bufs[3] = {sb, sb + GSTAGE, sb + 2 * GSTAGE};
    int cur = 0, nxt = 2;

    for (int ks = 0; ks < nk; ++ks) {
        CP_WAIT1();
        __syncthreads();

        if (ks + 2 < nk)
            gemm_load_stage(bufs[nxt], A, B, bm, bn, K, (ks + 2) * 32, tid);
        CP_COMMIT();

        const uint32_t sA = bufs[cur];
        const uint32_t sB = sA + GTILE;

#pragma unroll
        for (int kk = 0; kk < 2; ++kk) {
            const uint32_t colo = (uint32_t)(kk * 32 + (lane >> 4) * 16);
            uint32_t af[4][4], bf[4][2];
#pragma unroll
            for (int mi = 0; mi < 4; ++mi) {
                uint32_t ro = (uint32_t)(wr * 64 + mi * 16 + (lane & 15)) * 80 + colo;
                ldsm_x4(af[mi], sA + ro);
            }
#pragma unroll
            for (int nj = 0; nj < 2; ++nj) {
                uint32_t ro = (uint32_t)(wc * 32 + nj * 16 + (lane & 15)) * 80 + colo;
                uint32_t t[4];
                ldsm_x4(t, sB + ro);
                bf[nj * 2][0] = t[0]; bf[nj * 2][1] = t[2];
                bf[nj * 2 + 1][0] = t[1]; bf[nj * 2 + 1][1] = t[3];
            }
#pragma unroll
            for (int mi = 0; mi < 4; ++mi)
#pragma unroll
                for (int ni = 0; ni < 4; ++ni)
                    mma_f16(acc[mi][ni], af[mi], bf[ni]);
        }

        cur = (cur + 1) % 3;
        nxt = (nxt + 1) % 3;
    }

    // epilogue
#pragma unroll
    for (int mi = 0; mi < 4; ++mi) {
        int row = bm + wr * 64 + mi * 16 + (lane >> 2);
#pragma unroll
        for (int ni = 0; ni < 4; ++ni) {
            int col = bn + wc * 32 + ni * 8 + (lane & 3) * 2;
            if (HALF_OUT) {
                __half* C = (__half*)Cv;
                __half2 h0 = __floats2half2_rn(acc[mi][ni][0], acc[mi][ni][1]);
                __half2 h1 = __floats2half2_rn(acc[mi][ni][2], acc[mi][ni][3]);
                *(__half2*)&C[(size_t)row * N + col] = h0;
                *(__half2*)&C[(size_t)(row + 8) * N + col] = h1;
            } else {
                float* C = (float*)Cv;
                float2 v0 = make_float2(acc[mi][ni][0], acc[mi][ni][1]);
                float2 v1 = make_float2(acc[mi][ni][2], acc[mi][ni][3]);
                *(float2*)&C[(size_t)row * N + col] = v0;
                *(float2*)&C[(size_t)(row + 8) * N + col] = v1;
            }
        }
    }
}

// ---------------------------------------------------------------------------
// Prep: RoPE (q,k) + head-major relayout (B,H,T,D). Reads fp16 qkv.
// Q scale folds 1/8 AND log2(e) (flash uses exp2 domain).
// ---------------------------------------------------------------------------
#define QSCALE (0.125f * 1.4426950408889634f)

__global__ void rope_split_kernel(const __half* __restrict__ qkv,
                                  __half* __restrict__ Qh,
                                  __half* __restrict__ Kh, __half* __restrict__ Vh)
{
    int idx = blockIdx.x * blockDim.x + threadIdx.x;
    int i = idx & 31;
    int h = (idx >> 5) & 15;
    int t = (idx >> 9) & 2047;
    int b = idx >> 20;

    float p = powf(10000.0f, (float)(2 * i) * (1.0f / 64.0f));
    float ang = (float)t * (1.0f / p);
    float sn, cs;
    sincosf(ang, &sn, &cs);

    size_t src = ((size_t)(b * T_SEQ + t)) * QKV_COLS + h * D_HEAD;
    size_t dst = ((size_t)((b * H_DIM + h) * T_SEQ + t)) * D_HEAD;

    // q (fold 1/8 * log2e scale)
    {
        float q1 = __half2float(qkv[src + i]);
        float q2 = __half2float(qkv[src + i + 32]);
        Qh[dst + i]      = __float2half_rn((q1 * cs + q2 * sn) * QSCALE);
        Qh[dst + i + 32] = __float2half_rn((-q1 * sn + q2 * cs) * QSCALE);
    }
    // k
    {
        float k1 = __half2float(qkv[src + C_DIM + i]);
        float k2 = __half2float(qkv[src + C_DIM + i + 32]);
        Kh[dst + i]      = __float2half_rn(k1 * cs + k2 * sn);
        Kh[dst + i + 32] = __float2half_rn(-k1 * sn + k2 * cs);
    }
    // v (pass-through)
    {
        Vh[dst + i]      = qkv[src + 2 * C_DIM + i];
        Vh[dst + i + 32] = qkv[src + 2 * C_DIM + i + 32];
    }
}

// ---------------------------------------------------------------------------
// Flash attention via mma.sync fp16, causal, exp2 domain.
// CTA: 128 queries x one (b,h); 8 warps x 16 rows. 64-key tiles,
// 3-stage cp.async pipeline. Row sums computed by mma via ones in the
// V-row padding (cols 64-71 of the 72-half row) -> accumulator o[8].
// ---------------------------------------------------------------------------
#define FPITCH 144u
#define FTILE  (64u * FPITCH)          // 9216
#define FSTAGE (2u * FTILE)            // Kh, Vh = 18432
#define FL_SMEM (3u * FSTAGE + 256u)   // 55552 (pad for safety)

__device__ __forceinline__ void flash_load_stage(
    uint32_t dstbase, int kb,
    const __half* __restrict__ Kh, const __half* __restrict__ Vh, int tid)
{
#pragma unroll
    for (int j = 0; j < 4; ++j) {
        int idx = tid + j * 256;
        int tile = idx >> 9;                   // 0..1
        int r = (idx >> 3) & 63;
        int c = idx & 7;
        uint32_t dst = dstbase + (uint32_t)tile * FTILE + (uint32_t)r * FPITCH + c * 16;
        const __half* src = (tile == 0 ? Kh : Vh);
        CP_ASYNC16(dst, src + (size_t)(kb + r) * D_HEAD + c * 8);
    }
}

__global__ void __launch_bounds__(256, 2) flash_mma_kernel(
    const __half* __restrict__ Qhg,
    const __half* __restrict__ Khg, const __half* __restrict__ Vhg,
    __half* __restrict__ yh)
{
    extern __shared__ char fsm[];
    const uint32_t sb = smem_to_u32(fsm);
    const int tid = threadIdx.x;
    const int lane = tid & 31, w = tid >> 5;
    const int qt = gridDim.x - 1 - blockIdx.x;     // heavy tiles first
    const int bh = blockIdx.y;
    const int qb = qt * 128;

    const size_t hoff = (size_t)bh * T_SEQ * D_HEAD;
    const __half* Qh = Qhg + hoff + (size_t)qb * D_HEAD;
    const __half* Kh = Khg + hoff;
    const __half* Vh = Vhg + hoff;

    // ---- stage Q and extract A fragments ----
#pragma unroll
    for (int j = 0; j < 4; ++j) {
        int idx = tid + j * 256;               // 1024 chunks: 128 rows x 8
        int r = idx >> 3;
        int c = idx & 7;
        uint32_t dst = sb + (uint32_t)r * FPITCH + c * 16;
        CP_ASYNC16(dst, Qh + (size_t)r * D_HEAD + c * 8);
    }
    CP_COMMIT();
    CP_WAIT0();
    __syncthreads();

    uint32_t qhf[4][4];
    {
        uint32_t arow = (uint32_t)(w * 16 + (lane & 7) + ((lane & 8) ? 8 : 0));
        uint32_t acol = (uint32_t)(((lane & 16) ? 16 : 0));
#pragma unroll
        for (int kk = 0; kk < 4; ++kk)
            ldsm_x4(qhf[kk], sb + arow * FPITCH + kk * 32 + acol);
    }
    __syncthreads();   // Q fragments extracted; smem reusable

    // ---- fill V-row padding (cols 64-71) with fp16 ones in all 3 buffers ----
    {
        const uint4 ones = make_uint4(0x3C003C00u, 0x3C003C00u,
                                      0x3C003C00u, 0x3C003C00u);
        for (int idx = tid; idx < 192; idx += 256) {
            int bfi = idx >> 6;          // buffer 0..2
            int r = idx & 63;            // row
            uint32_t off = (uint32_t)bfi * FSTAGE + FTILE + (uint32_t)r * FPITCH + 128;
            *(uint4*)(fsm + off) = ones;
        }
    }

    // o[0..7] = output dims; o[8] = row-sum accumulator (ones column)
    float o[9][4];
#pragma unroll
    for (int j = 0; j < 9; ++j)
#pragma unroll
        for (int c = 0; c < 4; ++c) o[j][c] = 0.f;
    float m0 = -1e30f, m1 = -1e30f;

    const int ntiles = 2 * qt + 2;
    const int wqmin = qb + w * 16;
    const int wqmax = wqmin + 15;

    flash_load_stage(sb, 0, Kh, Vh, tid);
    CP_COMMIT();
    flash_load_stage(sb + FSTAGE, 64, Kh, Vh, tid);
    CP_COMMIT();

    uint32_t bufs[3] = {sb, sb + FSTAGE, sb + 2 * FSTAGE};
    int cur = 0, nxt = 2;

    for (int kt = 0; kt < ntiles; ++kt) {
        CP_WAIT1();
        __syncthreads();

        if (kt + 2 < ntiles)
            flash_load_stage(bufs[nxt], (kt + 2) * 64, Kh, Vh, tid);
        CP_COMMIT();

        const uint32_t stage = bufs[cur];
        const int kb = kt * 64;

        if (kb <= wqmax) {
            // ---- S = Q K^T (single pass, exp2-domain logits) ----
            float s[8][4];
#pragma unroll
            for (int j = 0; j < 8; ++j)
#pragma unroll
                for (int c = 0; c < 4; ++c) s[j][c] = 0.f;

            const uint32_t br = (uint32_t)((lane & 7) + ((lane & 16) ? 8 : 0));
            const uint32_t bc = (uint32_t)((lane & 8) ? 16 : 0);
#pragma unroll
            for (int kg = 0; kg < 4; ++kg) {
                uint32_t rowa = (uint32_t)(kg * 16) + br;
#pragma unroll
                for (int kk = 0; kk < 4; ++kk) {
                    uint32_t addr = stage + rowa * FPITCH + kk * 32 + bc;
                    uint32_t k4[4];
                    ldsm_x4(k4, addr);
                    mma_f16(s[2 * kg],     qhf[kk], &k4[0]);
                    mma_f16(s[2 * kg + 1], qhf[kk], &k4[2]);
                }
            }

            // ---- causal mask ----
            if (kb + 63 > wqmin) {
                int r0 = wqmin + (lane >> 2), r1 = r0 + 8;
#pragma unroll
                for (int j = 0; j < 8; ++j) {
                    int k0 = kb + j * 8 + ((lane & 3) << 1);
                    if (k0 > r0)     s[j][0] = -1e30f;
                    if (k0 + 1 > r0) s[j][1] = -1e30f;
                    if (k0 > r1)     s[j][2] = -1e30f;
                    if (k0 + 1 > r1) s[j][3] = -1e30f;
                }
            }

            // ---- online softmax (exp2 domain) ----
            float mx0 = -1e30f, mx1 = -1e30f;
#pragma unroll
            for (int j = 0; j < 8; ++j) {
                mx0 = fmaxf(mx0, fmaxf(s[j][0], s[j][1]));
                mx1 = fmaxf(mx1, fmaxf(s[j][2], s[j][3]));
            }
            mx0 = fmaxf(mx0, __shfl_xor_sync(0xffffffffu, mx0, 1));
            mx0 = fmaxf(mx0, __shfl_xor_sync(0xffffffffu, mx0, 2));
            mx1 = fmaxf(mx1, __shfl_xor_sync(0xffffffffu, mx1, 1));
            mx1 = fmaxf(mx1, __shfl_xor_sync(0xffffffffu, mx1, 2));
            float m0n = fmaxf(m0, mx0), m1n = fmaxf(m1, mx1);
            float sc0 = ex2f(m0 - m0n), sc1 = ex2f(m1 - m1n);
#pragma unroll
            for (int j = 0; j < 8; ++j) {
                s[j][0] = ex2f(s[j][0] - m0n);
                s[j][1] = ex2f(s[j][1] - m0n);
                s[j][2] = ex2f(s[j][2] - m1n);
                s[j][3] = ex2f(s[j][3] - m1n);
            }
            m0 = m0n; m1 = m1n;
#pragma unroll
            for (int j = 0; j < 9; ++j) {
                o[j][0] *= sc0; o[j][1] *= sc0;
                o[j][2] *= sc1; o[j][3] *= sc1;
            }

            // ---- pack P fp16 A-fragments ----
            uint32_t aph[4][4];
#pragma unroll
            for (int kk2 = 0; kk2 < 4; ++kk2) {
                int j0 = 2 * kk2, j1 = j0 + 1;
                __half2 p0 = __floats2half2_rn(s[j0][0], s[j0][1]);
                __half2 p1 = __floats2half2_rn(s[j0][2], s[j0][3]);
                __half2 p2 = __floats2half2_rn(s[j1][0], s[j1][1]);
                __half2 p3 = __floats2half2_rn(s[j1][2], s[j1][3]);
                aph[kk2][0] = *(uint32_t*)&p0;
                aph[kk2][1] = *(uint32_t*)&p1;
                aph[kk2][2] = *(uint32_t*)&p2;
                aph[kk2][3] = *(uint32_t*)&p3;
            }

            // ---- O += P V; row sums via ones column (o[8]) ----
            const uint32_t vr = (uint32_t)((lane & 7) + ((lane & 8) ? 8 : 0));
            const uint32_t vc = (uint32_t)((lane & 16) ? 16 : 0);
#pragma unroll
            for (int kk2 = 0; kk2 < 4; ++kk2) {
                uint32_t rowoff = stage + FTILE + (uint32_t)(kk2 * 16 + vr) * FPITCH;
#pragma unroll
                for (int dg = 0; dg < 4; ++dg) {
                    uint32_t v4[4];
                    ldsm_x4t(v4, rowoff + dg * 32 + vc);
                    mma_f16(o[2 * dg],     aph[kk2], &v4[0]);
                    mma_f16(o[2 * dg + 1], aph[kk2], &v4[2]);
                }
                // ones column (V pad cols 64-71). All lanes address offset
                // +128 (valid, in-row). v4[0]/v4[1] = k-rows 0-15 of the ones
                // n-group -- the correct B pair; v4[2]/v4[3] unused.
                {
                    uint32_t v4[4];
                    ldsm_x4t(v4, rowoff + 128);
                    mma_f16(o[8], aph[kk2], &v4[0]);
                }
            }
        }

        cur = (cur + 1) % 3;
        nxt = (nxt + 1) % 3;
    }

    // ---- normalize and write fp16 (proj GEMM A-operand) ----
    const float inv0 = 1.0f / o[8][0], inv1 = 1.0f / o[8][2];
    const int b = bh >> 4, h = bh & 15;
    const int r0 = qb + w * 16 + (lane >> 2);
#pragma unroll
    for (int j = 0; j < 8; ++j) {
        int col = h * 64 + j * 8 + (lane & 3) * 2;
        __half2 hh0 = __floats2half2_rn(o[j][0] * inv0, o[j][1] * inv0);
        __half2 hh1 = __floats2half2_rn(o[j][2] * inv1, o[j][3] * inv1);
        *(__half2*)&yh[(size_t)(b * T_SEQ + r0) * C_DIM + col] = hh0;
        *(__half2*)&yh[(size_t)(b * T_SEQ + r0 + 8) * C_DIM + col] = hh1;
    }
}

// ---------------------------------------------------------------------------
extern "C" void kernel_launch(void* const* d_in, const int* in_sizes, int n_in,
                              void* d_out, int out_size)
{
    const float* x      = (const float*)d_in[0];
    const float* w_attn = (const float*)d_in[1];
    const float* w_proj = (const float*)d_in[2];
    float* out = (float*)d_out;

    __half *qkv16, *x16, *wa, *wp, *yh;
    __half *Qh, *Kh, *Vh;
    cudaGetSymbolAddress((void**)&qkv16, g_qkv16);
    cudaGetSymbolAddress((void**)&x16, g_x16);
    cudaGetSymbolAddress((void**)&wa, g_wa);
    cudaGetSymbolAddress((void**)&wp, g_wp);
    cudaGetSymbolAddress((void**)&yh, g_yh);
    cudaGetSymbolAddress((void**)&Qh, g_Qh);
    cudaGetSymbolAddress((void**)&Kh, g_Kh);
    cudaGetSymbolAddress((void**)&Vh, g_Vh);

    static bool attr_set = false;
    if (!attr_set) {
        cudaFuncSetAttribute(gemm_f16_kernel<true>,
                             cudaFuncAttributeMaxDynamicSharedMemorySize, GEMM_SMEM);
        cudaFuncSetAttribute(gemm_f16_kernel<false>,
                             cudaFuncAttributeMaxDynamicSharedMemorySize, GEMM_SMEM);
        cudaFuncSetAttribute(flash_mma_kernel,
                             cudaFuncAttributeMaxDynamicSharedMemorySize, FL_SMEM);
        attr_set = true;
    }

    // fused input conversions (1 launch)
    conv_all_kernel<<<N4_ALL / 256, 256>>>(x, w_attn, w_proj, x16, wa, wp);

    // 1) qkv = x @ w_attn^T   (fp16 HMMA, fp16 output)
    {
        dim3 grid(QKV_COLS / 128, M_ROWS / 128);
        gemm_f16_kernel<true><<<grid, 256, GEMM_SMEM>>>(x16, wa, qkv16,
                                                        QKV_COLS, C_DIM);
    }
    // 2) RoPE + relayout (fp16 in/out; Q scaled by 1/8*log2e)
    {
        int total = B_DIM * T_SEQ * H_DIM * 32;
        rope_split_kernel<<<total / 256, 256>>>(qkv16, Qh, Kh, Vh);
    }
    // 3) flash attention (tensor cores) -> yh fp16
    {
        dim3 grid(T_SEQ / 128, B_DIM * H_DIM);
        flash_mma_kernel<<<grid, 256, FL_SMEM>>>(Qh, Kh, Vh, yh);
    }
    // 4) out = y @ w_proj^T   (fp16 HMMA, fp32 output)
    {
        dim3 grid(C_DIM / 128, M_ROWS / 128);
        gemm_f16_kernel<false><<<grid, 256, GEMM_SMEM>>>(yh, wp, out,
                                                         C_DIM, C_DIM);
    }
}